// round 14
// baseline (speedup 1.0000x reference)
#include <cuda_runtime.h>
#include <cuda_bf16.h>
#include <math.h>

#define D 512
#define NROWS 65536
#define MATN (D*D)
#define BARY_ITERS 6
#define SPLITS 32
#define CHUNK (NROWS/SPLITS)
#define NCTA 148
#define KC 64
#define PC 68
#define TILEB 8192
#define BUFSZ 32768
#define SMEM_DYN 65536

// Taylor coefficients of (1+u)^(-1/2) and (1+u)^(1/2), degree 6
#define IC0 1.0f
#define IC1 (-0.5f)
#define IC2 0.375f
#define IC3 (-0.3125f)
#define IC4 0.2734375f
#define IC5 (-0.24609375f)
#define IC6 0.2255859375f
#define SC0 1.0f
#define SC1 0.5f
#define SC2 (-0.125f)
#define SC3 0.0625f
#define SC4 (-0.0390625f)
#define SC5 0.02734375f
#define SC6 (-0.0205078125f)

// ---------------- matrix buffer ids ----------------
enum {
  COVC=0, COVS, SIGB, SE, SE2, SE3, SUZ, SUY, SZ, SY,
  BP0, BP1, BM0, BM1,
  ME0, ME20, ME30, MU0, ME1, ME21, ME31, MU1,
  BV, BR0, BT0, NBUF
};

__device__ float g_mat[NBUF][MATN];
__device__ __nv_bfloat16 g_h[NBUF][MATN];
__device__ __nv_bfloat16 g_l[NBUF][MATN];
__device__ float g_covpart[2*SPLITS][MATN];
__device__ float g_meanpart[512][D];
__device__ float g_mean[3][D];
__device__ float g_tr[5][8];
__device__ __nv_bfloat16 g_xch[(size_t)NROWS * D];
__device__ __nv_bfloat16 g_xcl[(size_t)NROWS * D];
__device__ __nv_bfloat16 g_xsh[(size_t)NROWS * D];
__device__ __nv_bfloat16 g_xsl[(size_t)NROWS * D];

// ---------------- grid-wide barrier ----------------
__device__ unsigned g_bar_cnt;
__device__ unsigned g_bar_gen;

__device__ __forceinline__ unsigned ldcg_u32(const unsigned* p) {
    unsigned v;
    asm volatile("ld.global.cg.u32 %0, [%1];" : "=r"(v) : "l"(p) : "memory");
    return v;
}

__device__ __forceinline__ void gridsync() {
    __syncthreads();
    if (threadIdx.x == 0) {
        __threadfence();
        unsigned gen = ldcg_u32(&g_bar_gen);
        if (atomicAdd(&g_bar_cnt, 1u) == NCTA - 1u) {
            g_bar_cnt = 0u;
            __threadfence();
            atomicExch(&g_bar_gen, gen + 1u);
        } else {
            unsigned ns = 32;
            while (ldcg_u32(&g_bar_gen) == gen) {
                __nanosleep(ns);
                if (ns < 256) ns <<= 1;
            }
        }
        __threadfence();
    }
    __syncthreads();
}

// ---------------- low-level helpers ----------------
__device__ __forceinline__ unsigned sm32(const void* p) {
    return (unsigned)__cvta_generic_to_shared(p);
}
__device__ __forceinline__ void mbar_init(unsigned a) {
    asm volatile("mbarrier.init.shared.b64 [%0], 1;" :: "r"(a) : "memory");
}
__device__ __forceinline__ void mbar_expect(unsigned a, unsigned bytes) {
    asm volatile("mbarrier.arrive.expect_tx.shared.b64 _, [%0], %1;"
                 :: "r"(a), "r"(bytes) : "memory");
}
__device__ __forceinline__ void bulk8k(unsigned sdst, const void* gsrc, unsigned mbar) {
    asm volatile("cp.async.bulk.shared::cta.global.mbarrier::complete_tx::bytes "
                 "[%0], [%1], 8192, [%2];"
                 :: "r"(sdst), "l"(gsrc), "r"(mbar) : "memory");
}
__device__ __forceinline__ void mbar_wait(unsigned mbar, unsigned parity) {
    asm volatile(
        "{\n\t.reg .pred P;\n\t"
        "MWL_%=:\n\t"
        "mbarrier.try_wait.parity.acquire.cta.shared::cta.b64 P, [%0], %1;\n\t"
        "@!P bra MWL_%=;\n\t}"
        :: "r"(mbar), "r"(parity) : "memory");
}
__device__ __forceinline__ void ldsm4(unsigned r[4], const unsigned short* p) {
    asm volatile("ldmatrix.sync.aligned.m8n8.x4.shared.b16 {%0,%1,%2,%3}, [%4];"
                 : "=r"(r[0]), "=r"(r[1]), "=r"(r[2]), "=r"(r[3]) : "r"(sm32(p)));
}
__device__ __forceinline__ void ldsm4t(unsigned r[4], const unsigned short* p) {
    asm volatile("ldmatrix.sync.aligned.m8n8.x4.trans.shared.b16 {%0,%1,%2,%3}, [%4];"
                 : "=r"(r[0]), "=r"(r[1]), "=r"(r[2]), "=r"(r[3]) : "r"(sm32(p)));
}
__device__ __forceinline__ void mma16816(float c[4], const unsigned a[4],
                                         unsigned b0, unsigned b1) {
    asm volatile(
        "mma.sync.aligned.m16n8k16.row.col.f32.bf16.bf16.f32 "
        "{%0,%1,%2,%3}, {%4,%5,%6,%7}, {%8,%9}, {%0,%1,%2,%3};\n"
        : "+f"(c[0]), "+f"(c[1]), "+f"(c[2]), "+f"(c[3])
        : "r"(a[0]), "r"(a[1]), "r"(a[2]), "r"(a[3]), "r"(b0), "r"(b1));
}
__device__ __forceinline__ void split2(float x0, float x1, unsigned &h, unsigned &l) {
    __nv_bfloat162 hh = __floats2bfloat162_rn(x0, x1);
    float r0 = x0 - __low2float(hh);
    float r1 = x1 - __high2float(hh);
    __nv_bfloat162 ll = __floats2bfloat162_rn(r0, r1);
    h = *reinterpret_cast<unsigned*>(&hh);
    l = *reinterpret_cast<unsigned*>(&ll);
}
__device__ __forceinline__ void split1(float x, unsigned short &h, unsigned short &l) {
    __nv_bfloat16 hb = __float2bfloat16_rn(x);
    float r = x - __bfloat162float(hb);
    __nv_bfloat16 lb = __float2bfloat16_rn(r);
    h = *reinterpret_cast<unsigned short*>(&hb);
    l = *reinterpret_cast<unsigned short*>(&lb);
}

__device__ __forceinline__ float get_c(int slot) {
    float s = 0.f;
    #pragma unroll
    for (int i = 0; i < 8; i++) s += __ldcg(&g_tr[slot][i]);
    return s * (1.0f / 512.0f);
}

__device__ __forceinline__ size_t thl_off(int m, int n) {
    unsigned tile = (((unsigned)m >> 6) << 3) + ((unsigned)n >> 6);
    unsigned off = (((unsigned)m & 63u) << 7) | (((unsigned)n & 63u) << 1);
    off ^= (off >> 3) & 0x70;
    return ((size_t)tile << 13) + off;
}

__device__ __forceinline__ void store_hl(__nv_bfloat16* H, __nv_bfloat16* L,
                                         int m, int n,
                                         float o0, float o1, float o2, float o3) {
    size_t t = thl_off(m, n);
    unsigned h0, l0, h1, l1;
    split2(o0, o1, h0, l0);
    split2(o2, o3, h1, l1);
    *(unsigned*)((char*)H + t)     = h0;
    *(unsigned*)((char*)H + t + 4) = h1;
    *(unsigned*)((char*)L + t)     = l0;
    *(unsigned*)((char*)L + t + 4) = l1;
}

__device__ __forceinline__ const unsigned short* swp(const char* sbuf, int plane,
                                                     int r, int c) {
    unsigned off = (((unsigned)r) << 7) + (((unsigned)c) << 1);
    off ^= (off >> 3) & 0x70;
    return (const unsigned short*)(sbuf + plane * TILEB + off);
}

// ---------------- pipeline ----------------
struct Pipe {
    unsigned mb0, mb1;
    unsigned par;
    char* sm;
};

__device__ __forceinline__ void stage_tiles(Pipe& pp, int buf,
    const __nv_bfloat16* AH, const __nv_bfloat16* AL,
    const __nv_bfloat16* BH, const __nv_bfloat16* BL,
    int aT, int bT)
{
    if (threadIdx.x == 0) {
        unsigned mbar = buf ? pp.mb1 : pp.mb0;
        mbar_expect(mbar, (unsigned)BUFSZ);
        unsigned d = sm32(pp.sm + buf * BUFSZ);
        bulk8k(d,             (const char*)AH + (size_t)aT * TILEB, mbar);
        bulk8k(d + TILEB,     (const char*)AL + (size_t)aT * TILEB, mbar);
        bulk8k(d + 2 * TILEB, (const char*)BH + (size_t)bT * TILEB, mbar);
        bulk8k(d + 3 * TILEB, (const char*)BL + (size_t)bT * TILEB, mbar);
    }
}

// dual-accumulator mma: hh + hl products -> c, lh product -> c2
__device__ __forceinline__ void mma_planes(float c[2][2][4], float c2[2][2][4],
                                           const char* sbuf,
                                           int wm, int wn, int trans) {
    int l = threadIdx.x & 31;
    #pragma unroll
    for (int kb = 0; kb < KC; kb += 16) {
        unsigned ah0[4], ah1[4], al0[4], al1[4], bh[4], bl[4];
        if (!trans) {
            int ar = (l & 7) + ((l & 8) ? 8 : 0);
            int ac = kb + ((l & 16) ? 8 : 0);
            ldsm4(ah0, swp(sbuf, 0, wm + ar, ac));
            ldsm4(ah1, swp(sbuf, 0, wm + 16 + ar, ac));
            ldsm4(al0, swp(sbuf, 1, wm + ar, ac));
            ldsm4(al1, swp(sbuf, 1, wm + 16 + ar, ac));
            int br = wn + (l & 7) + ((l & 16) ? 8 : 0);
            int bc = kb + ((l & 8) ? 8 : 0);
            ldsm4(bh, swp(sbuf, 2, br, bc));
            ldsm4(bl, swp(sbuf, 3, br, bc));
        } else {
            int tr = kb + (l & 7) + ((l & 16) ? 8 : 0);
            int ac = wm + ((l & 8) ? 8 : 0);
            ldsm4t(ah0, swp(sbuf, 0, tr, ac));
            ldsm4t(ah1, swp(sbuf, 0, tr, ac + 16));
            ldsm4t(al0, swp(sbuf, 1, tr, ac));
            ldsm4t(al1, swp(sbuf, 1, tr, ac + 16));
            int br = kb + (l & 7) + ((l & 8) ? 8 : 0);
            int bc = wn + ((l & 16) ? 8 : 0);
            ldsm4t(bh, swp(sbuf, 2, br, bc));
            ldsm4t(bl, swp(sbuf, 3, br, bc));
        }
        mma16816(c[0][0], ah0, bh[0], bh[1]);
        mma16816(c[0][1], ah0, bh[2], bh[3]);
        mma16816(c[1][0], ah1, bh[0], bh[1]);
        mma16816(c[1][1], ah1, bh[2], bh[3]);
        mma16816(c2[0][0], al0, bh[0], bh[1]);
        mma16816(c2[0][1], al0, bh[2], bh[3]);
        mma16816(c2[1][0], al1, bh[0], bh[1]);
        mma16816(c2[1][1], al1, bh[2], bh[3]);
        mma16816(c[0][0], ah0, bl[0], bl[1]);
        mma16816(c[0][1], ah0, bl[2], bl[3]);
        mma16816(c[1][0], ah1, bl[0], bl[1]);
        mma16816(c[1][1], ah1, bl[2], bl[3]);
    }
}

__device__ __forceinline__ void frags_to_Cs(float c[2][2][4], float* Cs, int wm, int wn) {
    int l = threadIdx.x & 31;
    int rr = l >> 2, cc2 = (l & 3) * 2;
    #pragma unroll
    for (int mf = 0; mf < 2; mf++)
        #pragma unroll
        for (int nf = 0; nf < 2; nf++) {
            int r = wm + mf * 16 + rr, cc = wn + nf * 8 + cc2;
            *(float2*)&Cs[r * PC + cc]       = make_float2(c[mf][nf][0], c[mf][nf][1]);
            *(float2*)&Cs[(r + 8) * PC + cc] = make_float2(c[mf][nf][2], c[mf][nf][3]);
        }
}

__device__ __forceinline__ void run_tile_acc(float c[2][2][4],
    const __nv_bfloat16* AH, const __nv_bfloat16* AL,
    const __nv_bfloat16* BH, const __nv_bfloat16* BL,
    int aBase, int aStr, int bBase, int bStr, int nch, int trans, Pipe& pp)
{
    int wid = threadIdx.x >> 5;
    int wm = (wid >> 2) * 32, wn = (wid & 3) * 16;
    float c2[2][2][4] = {};
    stage_tiles(pp, 0, AH, AL, BH, BL, aBase, bBase);
    #pragma unroll 1
    for (int kc = 0; kc < nch; kc++) {
        int cur = kc & 1;
        if (kc < nch - 1)
            stage_tiles(pp, cur ^ 1, AH, AL, BH, BL,
                        aBase + (kc + 1) * aStr, bBase + (kc + 1) * bStr);
        unsigned mbar = cur ? pp.mb1 : pp.mb0;
        mbar_wait(mbar, (pp.par >> cur) & 1u);
        pp.par ^= 1u << cur;
        mma_planes(c, c2, pp.sm + cur * BUFSZ, wm, wn, trans);
        __syncthreads();
    }
    #pragma unroll
    for (int i = 0; i < 2; i++)
        #pragma unroll
        for (int j = 0; j < 2; j++)
            #pragma unroll
            for (int k = 0; k < 4; k++)
                c[i][j][k] += c2[i][j][k];
}

__device__ __forceinline__ void run_tile(float c[2][2][4],
    const __nv_bfloat16* AH, const __nv_bfloat16* AL,
    const __nv_bfloat16* BH, const __nv_bfloat16* BL,
    int aBase, int aStr, int bBase, int bStr, int nch, int trans, Pipe& pp)
{
    run_tile_acc(c, AH, AL, BH, BL, aBase, aStr, bBase, bStr, nch, trans, pp);
    int wid = threadIdx.x >> 5;
    frags_to_Cs(c, (float*)pp.sm, (wid >> 2) * 32, (wid & 3) * 16);
    __syncthreads();
}

// ---------------- generic tile GEMM (alpha, trace, optional fp32) -------
__device__ __noinline__ void tile_gemm(int Aid, int Bid, int Cid,
                                       int m0, int n0, float alpha,
                                       int mirror, int trSlot, int wantF32,
                                       Pipe& pp)
{
    float* Cs = (float*)pp.sm;
    int tid = threadIdx.x;
    float c[2][2][4] = {};
    run_tile(c, g_h[Aid], g_l[Aid], g_h[Bid], g_l[Bid],
             (m0 >> 6) * 8, 1, (n0 >> 6) * 8, 1, 8, 0, pp);
    float* C = g_mat[Cid];
    __nv_bfloat16* CH = g_h[Cid];
    __nv_bfloat16* CL = g_l[Cid];
    int r = tid >> 2;
    float dsum = 0.f;
    #pragma unroll
    for (int q = 0; q < 4; q++) {
        int cc = (tid & 3) * 4 + q * 16;
        float4 v = *(float4*)&Cs[r * PC + cc];
        int m = m0 + r, n = n0 + cc;
        float o[4] = {v.x * alpha, v.y * alpha, v.z * alpha, v.w * alpha};
        #pragma unroll
        for (int j = 0; j < 4; j++)
            if (m == n + j) dsum += o[j];
        if (wantF32)
            *(float4*)&C[(size_t)m * D + n] = make_float4(o[0], o[1], o[2], o[3]);
        store_hl(CH, CL, m, n, o[0], o[1], o[2], o[3]);
    }
    if (mirror) {
        #pragma unroll
        for (int q = 0; q < 4; q++) {
            int cc = (tid & 3) * 4 + q * 16;
            float o[4];
            #pragma unroll
            for (int j = 0; j < 4; j++)
                o[j] = alpha * Cs[(cc + j) * PC + r];
            int row = n0 + r, col = m0 + cc;
            if (wantF32)
                *(float4*)&C[(size_t)row * D + col] = make_float4(o[0], o[1], o[2], o[3]);
            store_hl(CH, CL, row, col, o[0], o[1], o[2], o[3]);
        }
    }
    if (trSlot >= 0) {
        __syncthreads();
        float* red = (float*)pp.sm;
        red[tid] = dsum;
        __syncthreads();
        for (int off = 128; off > 0; off >>= 1) {
            if (tid < off) red[tid] += red[tid + off];
            __syncthreads();
        }
        if (tid == 0) g_tr[trSlot][m0 >> 6] = red[0];
    }
    __syncthreads();
}

// ---------------- powA: G=S@S -> E = S*ic - I, E2 = G*ic^2 - 2S*ic + I ---
__device__ __noinline__ void tile_powA(int Sid, int Eid, int E2id, float ic,
                                       int m0, int n0, int mirror, Pipe& pp)
{
    float* Cs = (float*)pp.sm;
    int tid = threadIdx.x;
    float c[2][2][4] = {};
    run_tile(c, g_h[Sid], g_l[Sid], g_h[Sid], g_l[Sid],
             (m0 >> 6) * 8, 1, (n0 >> 6) * 8, 1, 8, 0, pp);
    const float* S = g_mat[Sid];
    float* E2f = g_mat[E2id];
    __nv_bfloat16 *Eh = g_h[Eid], *El = g_l[Eid];
    __nv_bfloat16 *E2h = g_h[E2id], *E2l = g_l[E2id];
    float ic2 = ic * ic;
    int r = tid >> 2;
    #pragma unroll
    for (int q = 0; q < 4; q++) {
        int cc = (tid & 3) * 4 + q * 16;
        int m = m0 + r, n = n0 + cc;
        float4 g = *(float4*)&Cs[r * PC + cc];
        float4 s = __ldcg((const float4*)&S[(size_t)m * D + n]);
        float ev[4], e2v[4];
        float gg[4] = {g.x, g.y, g.z, g.w};
        float ss[4] = {s.x, s.y, s.z, s.w};
        #pragma unroll
        for (int j = 0; j < 4; j++) {
            float dia = (m == n + j) ? 1.f : 0.f;
            ev[j]  = ss[j] * ic - dia;
            e2v[j] = gg[j] * ic2 - 2.f * ss[j] * ic + dia;
        }
        *(float4*)&E2f[(size_t)m * D + n] = make_float4(e2v[0], e2v[1], e2v[2], e2v[3]);
        store_hl(Eh, El, m, n, ev[0], ev[1], ev[2], ev[3]);
        store_hl(E2h, E2l, m, n, e2v[0], e2v[1], e2v[2], e2v[3]);
    }
    if (mirror) {
        #pragma unroll
        for (int q = 0; q < 4; q++) {
            int cc = (tid & 3) * 4 + q * 16;
            int row = n0 + r, col = m0 + cc;
            float4 s = __ldcg((const float4*)&S[(size_t)row * D + col]);
            float ss[4] = {s.x, s.y, s.z, s.w};
            float gg[4] = {Cs[(cc + 0) * PC + r], Cs[(cc + 1) * PC + r],
                           Cs[(cc + 2) * PC + r], Cs[(cc + 3) * PC + r]};
            float ev[4], e2v[4];
            #pragma unroll
            for (int j = 0; j < 4; j++) {
                ev[j]  = ss[j] * ic;
                e2v[j] = gg[j] * ic2 - 2.f * ss[j] * ic;
            }
            *(float4*)&E2f[(size_t)row * D + col] = make_float4(e2v[0], e2v[1], e2v[2], e2v[3]);
            store_hl(Eh, El, row, col, ev[0], ev[1], ev[2], ev[3]);
            store_hl(E2h, E2l, row, col, e2v[0], e2v[1], e2v[2], e2v[3]);
        }
    }
    __syncthreads();
}

// ---------------- powB: E3=E2@E -> store E3 h/l, Uy (sqrt tail), opt Uz --
__device__ __noinline__ void tile_powB(int Sid, int E2id, int Eid, int E3id,
                                       int UYid, int UZid, float ic,
                                       int m0, int n0, int mirror, Pipe& pp)
{
    float* Cs = (float*)pp.sm;
    int tid = threadIdx.x;
    float c[2][2][4] = {};
    run_tile(c, g_h[E2id], g_l[E2id], g_h[Eid], g_l[Eid],
             (m0 >> 6) * 8, 1, (n0 >> 6) * 8, 1, 8, 0, pp);
    const float* S = g_mat[Sid];
    const float* E2f = g_mat[E2id];
    __nv_bfloat16 *E3h = g_h[E3id], *E3l = g_l[E3id];
    __nv_bfloat16 *Uyh = g_h[UYid], *Uyl = g_l[UYid];
    __nv_bfloat16 *Uzh = (UZid >= 0) ? g_h[UZid] : 0;
    __nv_bfloat16 *Uzl = (UZid >= 0) ? g_l[UZid] : 0;
    int r = tid >> 2;
    #pragma unroll 1
    for (int half = 0; half < (mirror ? 2 : 1); half++) {
        #pragma unroll
        for (int q = 0; q < 4; q++) {
            int cc = (tid & 3) * 4 + q * 16;
            int m, n;
            float e3v[4];
            if (half == 0) {
                m = m0 + r; n = n0 + cc;
                float4 g = *(float4*)&Cs[r * PC + cc];
                e3v[0] = g.x; e3v[1] = g.y; e3v[2] = g.z; e3v[3] = g.w;
            } else {
                m = n0 + r; n = m0 + cc;
                e3v[0] = Cs[(cc + 0) * PC + r]; e3v[1] = Cs[(cc + 1) * PC + r];
                e3v[2] = Cs[(cc + 2) * PC + r]; e3v[3] = Cs[(cc + 3) * PC + r];
            }
            float4 s = __ldcg((const float4*)&S[(size_t)m * D + n]);
            float4 e2 = __ldcg((const float4*)&E2f[(size_t)m * D + n]);
            float ss[4] = {s.x, s.y, s.z, s.w};
            float e2v[4] = {e2.x, e2.y, e2.z, e2.w};
            float uy[4], uz[4];
            #pragma unroll
            for (int j = 0; j < 4; j++) {
                float dia = (m == n + j) ? 1.f : 0.f;
                float ev = ss[j] * ic - dia;
                uy[j] = SC3 * dia + SC4 * ev + SC5 * e2v[j] + SC6 * e3v[j];
                uz[j] = IC3 * dia + IC4 * ev + IC5 * e2v[j] + IC6 * e3v[j];
            }
            store_hl(E3h, E3l, m, n, e3v[0], e3v[1], e3v[2], e3v[3]);
            store_hl(Uyh, Uyl, m, n, uy[0], uy[1], uy[2], uy[3]);
            if (Uzh) store_hl(Uzh, Uzl, m, n, uz[0], uz[1], uz[2], uz[3]);
        }
    }
    __syncthreads();
}

// ---------------- polyC: C = scale*(E3@U + k0 I + k1 E + k2 E2) ----------
__device__ __noinline__ void tile_polyC(int E3id, int Uid, int Sid, int E2id,
                                        float ic, float k0, float k1, float k2,
                                        float scale, int Cid,
                                        int m0, int n0, int mirror, Pipe& pp)
{
    float* Cs = (float*)pp.sm;
    int tid = threadIdx.x;
    float c[2][2][4] = {};
    run_tile(c, g_h[E3id], g_l[E3id], g_h[Uid], g_l[Uid],
             (m0 >> 6) * 8, 1, (n0 >> 6) * 8, 1, 8, 0, pp);
    const float* S = g_mat[Sid];
    const float* E2f = g_mat[E2id];
    __nv_bfloat16 *CH = g_h[Cid], *CL = g_l[Cid];
    int r = tid >> 2;
    #pragma unroll 1
    for (int half = 0; half < (mirror ? 2 : 1); half++) {
        #pragma unroll
        for (int q = 0; q < 4; q++) {
            int cc = (tid & 3) * 4 + q * 16;
            int m, n;
            float gg[4];
            if (half == 0) {
                m = m0 + r; n = n0 + cc;
                float4 g = *(float4*)&Cs[r * PC + cc];
                gg[0] = g.x; gg[1] = g.y; gg[2] = g.z; gg[3] = g.w;
            } else {
                m = n0 + r; n = m0 + cc;
                gg[0] = Cs[(cc + 0) * PC + r]; gg[1] = Cs[(cc + 1) * PC + r];
                gg[2] = Cs[(cc + 2) * PC + r]; gg[3] = Cs[(cc + 3) * PC + r];
            }
            float4 s = __ldcg((const float4*)&S[(size_t)m * D + n]);
            float4 e2 = __ldcg((const float4*)&E2f[(size_t)m * D + n]);
            float ss[4] = {s.x, s.y, s.z, s.w};
            float e2v[4] = {e2.x, e2.y, e2.z, e2.w};
            float o[4];
            #pragma unroll
            for (int j = 0; j < 4; j++) {
                float dia = (m == n + j) ? 1.f : 0.f;
                float ev = ss[j] * ic - dia;
                o[j] = scale * (gg[j] + k0 * dia + k1 * ev + k2 * e2v[j]);
            }
            store_hl(CH, CL, m, n, o[0], o[1], o[2], o[3]);
        }
    }
    __syncthreads();
}

// ---------------- polyV: V = sum_j aj*(E3j@Uyj + sqrt-base_j) ------------
__device__ __noinline__ void tile_polyV(int E30, int U0, int S0, int E20, float ic0,
                                        int E31, int U1, int S1, int E21, float ic1,
                                        float a0, float a1, int Vid,
                                        int m0, int n0, int mirror, Pipe& pp)
{
    float* Cs = (float*)pp.sm;
    int tid = threadIdx.x;
    float c[2][2][4] = {};
    run_tile_acc(c, g_h[E30], g_l[E30], g_h[U0], g_l[U0],
                 (m0 >> 6) * 8, 1, (n0 >> 6) * 8, 1, 8, 0, pp);
    float r01 = a0 / a1;
    #pragma unroll
    for (int i = 0; i < 2; i++)
        #pragma unroll
        for (int j = 0; j < 2; j++)
            #pragma unroll
            for (int k = 0; k < 4; k++)
                c[i][j][k] *= r01;
    run_tile_acc(c, g_h[E31], g_l[E31], g_h[U1], g_l[U1],
                 (m0 >> 6) * 8, 1, (n0 >> 6) * 8, 1, 8, 0, pp);
    int wid = tid >> 5;
    frags_to_Cs(c, Cs, (wid >> 2) * 32, (wid & 3) * 16);
    __syncthreads();
    const float* S0f = g_mat[S0]; const float* E20f = g_mat[E20];
    const float* S1f = g_mat[S1]; const float* E21f = g_mat[E21];
    __nv_bfloat16 *CH = g_h[Vid], *CL = g_l[Vid];
    int r = tid >> 2;
    #pragma unroll 1
    for (int half = 0; half < (mirror ? 2 : 1); half++) {
        #pragma unroll
        for (int q = 0; q < 4; q++) {
            int cc = (tid & 3) * 4 + q * 16;
            int m, n;
            float gg[4];
            if (half == 0) {
                m = m0 + r; n = n0 + cc;
                float4 g = *(float4*)&Cs[r * PC + cc];
                gg[0] = g.x; gg[1] = g.y; gg[2] = g.z; gg[3] = g.w;
            } else {
                m = n0 + r; n = m0 + cc;
                gg[0] = Cs[(cc + 0) * PC + r]; gg[1] = Cs[(cc + 1) * PC + r];
                gg[2] = Cs[(cc + 2) * PC + r]; gg[3] = Cs[(cc + 3) * PC + r];
            }
            float4 s0 = __ldcg((const float4*)&S0f[(size_t)m * D + n]);
            float4 e20 = __ldcg((const float4*)&E20f[(size_t)m * D + n]);
            float4 s1 = __ldcg((const float4*)&S1f[(size_t)m * D + n]);
            float4 e21 = __ldcg((const float4*)&E21f[(size_t)m * D + n]);
            float ss0[4] = {s0.x, s0.y, s0.z, s0.w};
            float eb0[4] = {e20.x, e20.y, e20.z, e20.w};
            float ss1[4] = {s1.x, s1.y, s1.z, s1.w};
            float eb1[4] = {e21.x, e21.y, e21.z, e21.w};
            float o[4];
            #pragma unroll
            for (int j = 0; j < 4; j++) {
                float dia = (m == n + j) ? 1.f : 0.f;
                float ev0 = ss0[j] * ic0 - dia;
                float ev1 = ss1[j] * ic1 - dia;
                float b0 = SC0 * dia + SC1 * ev0 + SC2 * eb0[j];
                float b1 = SC0 * dia + SC1 * ev1 + SC2 * eb1[j];
                o[j] = a1 * gg[j] + a0 * b0 + a1 * b1;
            }
            store_hl(CH, CL, m, n, o[0], o[1], o[2], o[3]);
        }
    }
    __syncthreads();
}

// ---------------- phase runners ----------------
__device__ __forceinline__ void sym_decode(int tt, int &mt, int &nt) {
    int m = 0, r = tt;
    while (r >= 8 - m) { r -= 8 - m; m++; }
    mt = m; nt = m + r;
}

__device__ __noinline__ void phase_gemm(int nj, const int* A, const int* B,
                                        const int* Cid, float alpha,
                                        int sym, int tr0, int f32, Pipe& pp) {
    int tpj = sym ? 36 : 64;
    int total = nj * tpj;
    for (int t = blockIdx.x; t < total; t += NCTA) {
        int j = t / tpj, tt = t - j * tpj;
        int mt, nt;
        if (sym) sym_decode(tt, mt, nt);
        else { mt = tt >> 3; nt = tt & 7; }
        int trSlot = (tr0 >= 0 && mt == nt) ? tr0 + j : -1;
        tile_gemm(A[j], B[j], Cid[j], mt * 64, nt * 64, alpha,
                  sym && (mt != nt), trSlot, f32, pp);
    }
}

__device__ __noinline__ void phase_powA(int nj, const int* S, const int* E,
                                        const int* E2, const float* ic, Pipe& pp) {
    int total = nj * 36;
    for (int t = blockIdx.x; t < total; t += NCTA) {
        int j = t / 36, tt = t - j * 36;
        int mt, nt;
        sym_decode(tt, mt, nt);
        tile_powA(S[j], E[j], E2[j], ic[j], mt * 64, nt * 64, mt != nt, pp);
    }
}

__device__ __noinline__ void phase_powB(int nj, const int* S, const int* E2,
                                        const int* E, const int* E3,
                                        const int* UY, const int* UZ,
                                        const float* ic, Pipe& pp) {
    int total = nj * 36;
    for (int t = blockIdx.x; t < total; t += NCTA) {
        int j = t / 36, tt = t - j * 36;
        int mt, nt;
        sym_decode(tt, mt, nt);
        tile_powB(S[j], E2[j], E[j], E3[j], UY[j], UZ[j], ic[j],
                  mt * 64, nt * 64, mt != nt, pp);
    }
}

__device__ __noinline__ void phase_polyC(int nj, const int* E3, const int* U,
                                         const int* S, const int* E2,
                                         const float* ic, const float* k0,
                                         const float* k1, const float* k2,
                                         const float* sc, const int* Cid, Pipe& pp) {
    int total = nj * 36;
    for (int t = blockIdx.x; t < total; t += NCTA) {
        int j = t / 36, tt = t - j * 36;
        int mt, nt;
        sym_decode(tt, mt, nt);
        tile_polyC(E3[j], U[j], S[j], E2[j], ic[j], k0[j], k1[j], k2[j],
                   sc[j], Cid[j], mt * 64, nt * 64, mt != nt, pp);
    }
}

__device__ __noinline__ void phase_polyV(float ic0, float ic1, float a0, float a1,
                                         Pipe& pp) {
    for (int t = blockIdx.x; t < 36; t += NCTA) {
        int mt, nt;
        sym_decode(t, mt, nt);
        tile_polyV(ME30, MU0, BM0, ME20, ic0, ME31, MU1, BM1, ME21, ic1,
                   a0, a1, BV, mt * 64, nt * 64, mt != nt, pp);
    }
}

// ---------------- trace of COVC ----------------
__device__ __noinline__ void trace_prep_covc() {
    __shared__ float red[256];
    int t = threadIdx.x;
    red[t] = __ldcg(&g_mat[COVC][(size_t)t * (D + 1)])
           + __ldcg(&g_mat[COVC][(size_t)(t + 256) * (D + 1)]);
    __syncthreads();
    for (int off = 128; off > 0; off >>= 1) {
        if (t < off) red[t] += red[t + off];
        __syncthreads();
    }
    if (t == 0) {
        g_tr[0][0] = red[0]; g_tr[4][0] = red[0];
        for (int i = 1; i < 8; i++) { g_tr[0][i] = 0.f; g_tr[4][i] = 0.f; }
    }
}

// sqrt+invsqrt of S -> SY (sqrt), SZ (invsqrt), 3 phases
__device__ void root_full(int Sid, float c, Pipe& pp) {
    float ic = 1.0f / c;
    int S1[1] = {Sid}, E1[1] = {SE}, E21[1] = {SE2};
    float icv[1] = {ic};
    phase_powA(1, S1, E1, E21, icv, pp);
    gridsync();
    int E31[1] = {SE3}, UY1[1] = {SUY}, UZ1[1] = {SUZ};
    phase_powB(1, S1, E21, E1, E31, UY1, UZ1, icv, pp);
    gridsync();
    int E3c[2] = {SE3, SE3}, Uc[2] = {SUZ, SUY};
    int Sc[2] = {Sid, Sid}, E2c[2] = {SE2, SE2}, Cc[2] = {SZ, SY};
    float icc[2] = {ic, ic};
    float k0c[2] = {IC0, SC0}, k1c[2] = {IC1, SC1}, k2c[2] = {IC2, SC2};
    float scc[2] = {rsqrtf(c), sqrtf(c)};
    phase_polyC(2, E3c, Uc, Sc, E2c, icc, k0c, k1c, k2c, scc, Cc, pp);
    gridsync();
}

// ---------------- persistent barycenter kernel ----------------
__global__ __launch_bounds__(256, 1) void persist_k() {
    extern __shared__ char sm_c[];
    __shared__ unsigned long long s_mbar[2];
    Pipe pp;
    pp.mb0 = sm32(&s_mbar[0]); pp.mb1 = sm32(&s_mbar[1]);
    pp.par = 0; pp.sm = sm_c;
    if (threadIdx.x == 0) { mbar_init(pp.mb0); mbar_init(pp.mb1); }
    __syncthreads();

    int A[2], B[2], C[2];

    if (blockIdx.x == 0) trace_prep_covc();
    gridsync();

    for (int it = 0; it < BARY_ITERS; it++) {
        int Sid = (it == 0) ? COVC : SIGB;
        float c = get_c(0);
        root_full(Sid, c, pp);          // SY = sqrt(S), SZ = invsqrt(S)

        // P_j = SY @ cov_j (full)
        A[0] = SY; B[0] = COVC; C[0] = BP0;
        A[1] = SY; B[1] = COVS; C[1] = BP1;
        phase_gemm(2, A, B, C, 1.f, 0, -1, 0, pp);
        gridsync();
        // M_j = P_j @ SY (sym, traces 1/2, fp32)
        A[0] = BP0; B[0] = SY; C[0] = BM0;
        A[1] = BP1; B[1] = SY; C[1] = BM1;
        phase_gemm(2, A, B, C, 1.f, 1, 1, 1, pp);
        gridsync();

        float c0 = get_c(1), c1 = get_c(2);
        float ic0 = 1.f / c0, ic1 = 1.f / c1;
        int Sm[2] = {BM0, BM1}, Em[2] = {ME0, ME1}, E2m[2] = {ME20, ME21};
        float icm[2] = {ic0, ic1};
        phase_powA(2, Sm, Em, E2m, icm, pp);
        gridsync();
        int E3m[2] = {ME30, ME31}, UYm[2] = {MU0, MU1}, UZm[2] = {-1, -1};
        phase_powB(2, Sm, E2m, Em, E3m, UYm, UZm, icm, pp);
        gridsync();
        // V = 0.5*sqrt(M0) + 0.5*sqrt(M1)
        phase_polyV(ic0, ic1, 0.5f * sqrtf(c0), 0.5f * sqrtf(c1), pp);
        gridsync();

        // R = SZ @ V (full)
        A[0] = SZ; B[0] = BV; C[0] = BR0;
        phase_gemm(1, A, B, C, 1.f, 0, -1, 0, pp);
        gridsync();
        // Sigma = R @ SZ (sym, trace 0, fp32)
        A[0] = BR0; B[0] = SZ; C[0] = SIGB;
        phase_gemm(1, A, B, C, 1.f, 1, 0, 1, pp);
        gridsync();
    }

    // ---- final: M = covc^-1/2 sqrt(covc^1/2 Sigma covc^1/2) covc^-1/2 ----
    float cc = get_c(4);
    root_full(COVC, cc, pp);

    A[0] = SY; B[0] = SIGB; C[0] = BP0;
    phase_gemm(1, A, B, C, 1.f, 0, -1, 0, pp);
    gridsync();
    A[0] = BP0; B[0] = SY; C[0] = BM0;
    phase_gemm(1, A, B, C, 1.f, 1, 1, 1, pp);
    gridsync();
    float cm = get_c(1);
    float icm1 = 1.f / cm;
    {
        int S1[1] = {BM0}, E1[1] = {ME0}, E21[1] = {ME20};
        float icv[1] = {icm1};
        phase_powA(1, S1, E1, E21, icv, pp);
        gridsync();
        int E31[1] = {ME30}, UY1[1] = {MU0}, UZ1[1] = {-1};
        phase_powB(1, S1, E21, E1, E31, UY1, UZ1, icv, pp);
        gridsync();
        int E3c[1] = {ME30}, Uc[1] = {MU0}, Sc[1] = {BM0}, E2c[1] = {ME20};
        int Cc[1] = {ME1};
        float icc[1] = {icm1};
        float k0c[1] = {SC0}, k1c[1] = {SC1}, k2c[1] = {SC2};
        float scc[1] = {sqrtf(cm)};
        phase_polyC(1, E3c, Uc, Sc, E2c, icc, k0c, k1c, k2c, scc, Cc, pp);
        gridsync();
    }

    A[0] = SZ; B[0] = ME1; C[0] = BR0;
    phase_gemm(1, A, B, C, 1.f, 0, -1, 0, pp);
    gridsync();
    A[0] = BR0; B[0] = SZ; C[0] = BT0;
    phase_gemm(1, A, B, C, 1.f, 1, -1, 0, pp);
}

// ---------------- pre-kernels ----------------
__global__ void colsum1_k(const float* __restrict__ content,
                          const float* __restrict__ style) {
    int cta = blockIdx.x, t = threadIdx.x;
    const float* x = (cta < 256) ? content : style;
    const float* base = x + (size_t)(cta & 255) * 256 * D;
    float s0 = 0.f, s1 = 0.f;
    for (int r = 0; r < 256; r++) {
        s0 += base[(size_t)r * D + t];
        s1 += base[(size_t)r * D + t + 256];
    }
    g_meanpart[cta][t] = s0;
    g_meanpart[cta][t + 256] = s1;
}

__global__ void colsum2_k() {
    int t = threadIdx.x;
    float sc = 0.f, ss = 0.f;
    for (int i = 0; i < 256; i++) {
        sc += g_meanpart[i][t];
        ss += g_meanpart[256 + i][t];
    }
    sc *= (1.0f / NROWS);
    ss *= (1.0f / NROWS);
    g_mean[0][t] = sc;
    g_mean[1][t] = ss;
    g_mean[2][t] = 0.5f * (sc + ss);
}

__global__ __launch_bounds__(256) void center_k(const float* __restrict__ content,
                                                const float* __restrict__ style) {
    int which = blockIdx.y;
    const float* x = which ? style : content;
    __nv_bfloat16* XH = which ? g_xsh : g_xch;
    __nv_bfloat16* XL = which ? g_xsl : g_xcl;
    size_t i = (size_t)blockIdx.x * 256 + threadIdx.x;
    float4 v = *((const float4*)x + i);
    int r = (int)(i >> 7);
    int col = (int)((i << 2) & 511);
    float4 mu = *(const float4*)&g_mean[which][col];
    store_hl(XH, XL, r, col, v.x - mu.x, v.y - mu.y, v.z - mu.z, v.w - mu.w);
}

// ---------------- Xc^T Xc partials ----------------
__global__ __launch_bounds__(256) void xtx_k() {
    if (blockIdx.y > blockIdx.x) return;
    extern __shared__ char sm_c[];
    __shared__ unsigned long long s_mbar[2];
    Pipe pp;
    pp.mb0 = sm32(&s_mbar[0]); pp.mb1 = sm32(&s_mbar[1]);
    pp.par = 0; pp.sm = sm_c;
    if (threadIdx.x == 0) { mbar_init(pp.mb0); mbar_init(pp.mb1); }
    __syncthreads();

    float* Cs = (float*)sm_c;
    int z = blockIdx.z;
    const __nv_bfloat16* XH = (z < 32) ? g_xch : g_xsh;
    const __nv_bfloat16* XL = (z < 32) ? g_xcl : g_xsl;
    int tid = threadIdx.x;
    int m0 = blockIdx.y * 64, n0 = blockIdx.x * 64;
    int rb0 = (z & 31) * (CHUNK / 64);
    float c[2][2][4] = {};
    run_tile(c, XH, XL, XH, XL,
             rb0 * 8 + (m0 >> 6), 8, rb0 * 8 + (n0 >> 6), 8, CHUNK / 64, 1, pp);
    float* Cp = g_covpart[z];
    int r = tid >> 2;
    #pragma unroll
    for (int q = 0; q < 4; q++) {
        int cc = (tid & 3) * 4 + q * 16;
        float4 v = *(float4*)&Cs[r * PC + cc];
        *(float4*)&Cp[(m0 + r) * D + n0 + cc] = v;
    }
}

__global__ void covfin_k() {
    int gidx = blockIdx.x * 256 + threadIdx.x;
    int which = gidx >= MATN;
    int idx = gidx & (MATN - 1);
    int base = which ? 32 : 0;
    int cov = which ? COVS : COVC;
    int m = idx >> 9, n = idx & 511;
    int ms = m, ns = n;
    if ((m >> 6) > (n >> 6)) { ms = n; ns = m; }
    float s = 0.f;
    #pragma unroll 8
    for (int p = 0; p < SPLITS; p++) s += g_covpart[base + p][ms * D + ns];
    float v = s * (1.0f / (NROWS - 1));
    g_mat[cov][idx] = v;
    unsigned short h, l;
    split1(v, h, l);
    size_t t = thl_off(m, n);
    *(unsigned short*)((char*)g_h[cov] + t) = h;
    *(unsigned short*)((char*)g_l[cov] + t) = l;
}

// ---------------- output GEMM: out = Xc @ M + mu_b ----------------------
__global__ __launch_bounds__(256) void outgemm_k(float* __restrict__ out) {
    extern __shared__ char sm_c[];
    __shared__ unsigned long long s_mbar[2];
    Pipe pp;
    pp.mb0 = sm32(&s_mbar[0]); pp.mb1 = sm32(&s_mbar[1]);
    pp.par = 0; pp.sm = sm_c;
    if (threadIdx.x == 0) { mbar_init(pp.mb0); mbar_init(pp.mb1); }
    __syncthreads();

    float* Cs = (float*)sm_c;
    int tid = threadIdx.x;
    size_t m0 = (size_t)blockIdx.y * 64;
    int n0 = blockIdx.x * 64;
    float c[2][2][4] = {};
    run_tile(c, g_xch, g_xcl, g_h[BT0], g_l[BT0],
             (int)(m0 >> 6) * 8, 1, (n0 >> 6) * 8, 1, 8, 0, pp);
    int r = tid >> 2;
    #pragma unroll
    for (int q = 0; q < 4; q++) {
        int cc = (tid & 3) * 4 + q * 16;
        float4 v = *(float4*)&Cs[r * PC + cc];
        float4 mb = *(const float4*)&g_mean[2][n0 + cc];
        v.x += mb.x; v.y += mb.y; v.z += mb.z; v.w += mb.w;
        *(float4*)&out[(m0 + (size_t)r) * D + n0 + cc] = v;
    }
}

// ---------------- host orchestration ----------------
extern "C" void kernel_launch(void* const* d_in, const int* in_sizes, int n_in,
                              void* d_out, int out_size) {
    const float* content = (const float*)d_in[0];
    const float* style   = (const float*)d_in[1];
    float* out = (float*)d_out;

    cudaFuncSetAttribute(persist_k, cudaFuncAttributeMaxDynamicSharedMemorySize, SMEM_DYN);
    cudaFuncSetAttribute(xtx_k, cudaFuncAttributeMaxDynamicSharedMemorySize, SMEM_DYN);
    cudaFuncSetAttribute(outgemm_k, cudaFuncAttributeMaxDynamicSharedMemorySize, SMEM_DYN);

    colsum1_k<<<512, 256>>>(content, style);                         // 0
    colsum2_k<<<1, D>>>();                                           // 1
    center_k<<<dim3(NROWS * D / 4 / 256, 2), 256>>>(content, style); // 2
    xtx_k<<<dim3(8, 8, 64), 256, SMEM_DYN>>>();                      // 3
    covfin_k<<<2 * MATN / 256, 256>>>();                             // 4
    persist_k<<<NCTA, 256, SMEM_DYN>>>();                            // 5
    outgemm_k<<<dim3(8, 1024), 256, SMEM_DYN>>>(out);                // 6

    (void)in_sizes; (void)n_in; (void)out_size;
}

// round 15
// speedup vs baseline: 1.1161x; 1.1161x over previous
#include <cuda_runtime.h>
#include <cuda_bf16.h>
#include <math.h>

#define D 512
#define NROWS 65536
#define MATN (D*D)
#define BARY_ITERS 6
#define SPLITS 32
#define CHUNK (NROWS/SPLITS)
#define NCTA 148
#define KC 64
#define PC 68
#define TILEB 8192
#define BUFSZ 32768
#define SMEM_DYN 65536

// deg-4 Chebyshev-economized coefficients of (1+u)^(1/2), (1+u)^(-1/2)
// Sigma-root set: economized on u in [-0.25, 0.25]
#define SQ0 0.99999984f
#define SQ1 0.499966621f
#define SQ2 (-0.124954939f)
#define SQ3 0.064636254f
#define SQ4 (-0.040985088f)
#define RZ0 1.000001721f
#define RZ1 (-0.499699593f)
#define RZ2 0.374504336f
#define RZ3 (-0.331726072f)
#define RZ4 0.294585882f
// middle-root sqrt set: economized on u in [-0.4, 0.4]
#define MQ0 0.999997375f
#define MQ1 0.49978125f
#define MQ2 (-0.124704687f)
#define MQ3 0.06796875f
#define MQ4 (-0.04398438f)

// ---------------- matrix buffer ids ----------------
enum {
  COVC=0, COVS, SIGB, SE, SE2, SUZ, SUY, SZ, SY,
  BP0, BP1, BM0, BM1,
  ME0, ME20, MU0, ME1, ME21, MU1,
  BV, BR0, BT0, NBUF
};

__device__ float g_mat[NBUF][MATN];
__device__ __nv_bfloat16 g_h[NBUF][MATN];
__device__ __nv_bfloat16 g_l[NBUF][MATN];
__device__ float g_covpart[2*SPLITS][MATN];
__device__ float g_meanpart[512][D];
__device__ float g_mean[3][D];
__device__ float g_tr[5][8];
__device__ __nv_bfloat16 g_xch[(size_t)NROWS * D];
__device__ __nv_bfloat16 g_xcl[(size_t)NROWS * D];
__device__ __nv_bfloat16 g_xsh[(size_t)NROWS * D];
__device__ __nv_bfloat16 g_xsl[(size_t)NROWS * D];

// ---------------- grid-wide barrier ----------------
__device__ unsigned g_bar_cnt;
__device__ unsigned g_bar_gen;

__device__ __forceinline__ unsigned ldcg_u32(const unsigned* p) {
    unsigned v;
    asm volatile("ld.global.cg.u32 %0, [%1];" : "=r"(v) : "l"(p) : "memory");
    return v;
}

__device__ __forceinline__ void gridsync() {
    __syncthreads();
    if (threadIdx.x == 0) {
        __threadfence();
        unsigned gen = ldcg_u32(&g_bar_gen);
        if (atomicAdd(&g_bar_cnt, 1u) == NCTA - 1u) {
            g_bar_cnt = 0u;
            __threadfence();
            atomicExch(&g_bar_gen, gen + 1u);
        } else {
            unsigned ns = 32;
            while (ldcg_u32(&g_bar_gen) == gen) {
                __nanosleep(ns);
                if (ns < 256) ns <<= 1;
            }
        }
        __threadfence();
    }
    __syncthreads();
}

// ---------------- low-level helpers ----------------
__device__ __forceinline__ unsigned sm32(const void* p) {
    return (unsigned)__cvta_generic_to_shared(p);
}
__device__ __forceinline__ void mbar_init(unsigned a) {
    asm volatile("mbarrier.init.shared.b64 [%0], 1;" :: "r"(a) : "memory");
}
__device__ __forceinline__ void mbar_expect(unsigned a, unsigned bytes) {
    asm volatile("mbarrier.arrive.expect_tx.shared.b64 _, [%0], %1;"
                 :: "r"(a), "r"(bytes) : "memory");
}
__device__ __forceinline__ void bulk8k(unsigned sdst, const void* gsrc, unsigned mbar) {
    asm volatile("cp.async.bulk.shared::cta.global.mbarrier::complete_tx::bytes "
                 "[%0], [%1], 8192, [%2];"
                 :: "r"(sdst), "l"(gsrc), "r"(mbar) : "memory");
}
__device__ __forceinline__ void mbar_wait(unsigned mbar, unsigned parity) {
    asm volatile(
        "{\n\t.reg .pred P;\n\t"
        "MWL_%=:\n\t"
        "mbarrier.try_wait.parity.acquire.cta.shared::cta.b64 P, [%0], %1;\n\t"
        "@!P bra MWL_%=;\n\t}"
        :: "r"(mbar), "r"(parity) : "memory");
}
__device__ __forceinline__ void ldsm4(unsigned r[4], const unsigned short* p) {
    asm volatile("ldmatrix.sync.aligned.m8n8.x4.shared.b16 {%0,%1,%2,%3}, [%4];"
                 : "=r"(r[0]), "=r"(r[1]), "=r"(r[2]), "=r"(r[3]) : "r"(sm32(p)));
}
__device__ __forceinline__ void ldsm4t(unsigned r[4], const unsigned short* p) {
    asm volatile("ldmatrix.sync.aligned.m8n8.x4.trans.shared.b16 {%0,%1,%2,%3}, [%4];"
                 : "=r"(r[0]), "=r"(r[1]), "=r"(r[2]), "=r"(r[3]) : "r"(sm32(p)));
}
__device__ __forceinline__ void mma16816(float c[4], const unsigned a[4],
                                         unsigned b0, unsigned b1) {
    asm volatile(
        "mma.sync.aligned.m16n8k16.row.col.f32.bf16.bf16.f32 "
        "{%0,%1,%2,%3}, {%4,%5,%6,%7}, {%8,%9}, {%0,%1,%2,%3};\n"
        : "+f"(c[0]), "+f"(c[1]), "+f"(c[2]), "+f"(c[3])
        : "r"(a[0]), "r"(a[1]), "r"(a[2]), "r"(a[3]), "r"(b0), "r"(b1));
}
__device__ __forceinline__ void split2(float x0, float x1, unsigned &h, unsigned &l) {
    __nv_bfloat162 hh = __floats2bfloat162_rn(x0, x1);
    float r0 = x0 - __low2float(hh);
    float r1 = x1 - __high2float(hh);
    __nv_bfloat162 ll = __floats2bfloat162_rn(r0, r1);
    h = *reinterpret_cast<unsigned*>(&hh);
    l = *reinterpret_cast<unsigned*>(&ll);
}
__device__ __forceinline__ void split1(float x, unsigned short &h, unsigned short &l) {
    __nv_bfloat16 hb = __float2bfloat16_rn(x);
    float r = x - __bfloat162float(hb);
    __nv_bfloat16 lb = __float2bfloat16_rn(r);
    h = *reinterpret_cast<unsigned short*>(&hb);
    l = *reinterpret_cast<unsigned short*>(&lb);
}

__device__ __forceinline__ float get_c(int slot) {
    float s = 0.f;
    #pragma unroll
    for (int i = 0; i < 8; i++) s += __ldcg(&g_tr[slot][i]);
    return s * (1.0f / 512.0f);
}

__device__ __forceinline__ size_t thl_off(int m, int n) {
    unsigned tile = (((unsigned)m >> 6) << 3) + ((unsigned)n >> 6);
    unsigned off = (((unsigned)m & 63u) << 7) | (((unsigned)n & 63u) << 1);
    off ^= (off >> 3) & 0x70;
    return ((size_t)tile << 13) + off;
}

__device__ __forceinline__ void store_hl(__nv_bfloat16* H, __nv_bfloat16* L,
                                         int m, int n,
                                         float o0, float o1, float o2, float o3) {
    size_t t = thl_off(m, n);
    unsigned h0, l0, h1, l1;
    split2(o0, o1, h0, l0);
    split2(o2, o3, h1, l1);
    *(unsigned*)((char*)H + t)     = h0;
    *(unsigned*)((char*)H + t + 4) = h1;
    *(unsigned*)((char*)L + t)     = l0;
    *(unsigned*)((char*)L + t + 4) = l1;
}

__device__ __forceinline__ const unsigned short* swp(const char* sbuf, int plane,
                                                     int r, int c) {
    unsigned off = (((unsigned)r) << 7) + (((unsigned)c) << 1);
    off ^= (off >> 3) & 0x70;
    return (const unsigned short*)(sbuf + plane * TILEB + off);
}

// ---------------- pipeline ----------------
struct Pipe {
    unsigned mb0, mb1;
    unsigned par;
    char* sm;
};

__device__ __forceinline__ void stage_tiles(Pipe& pp, int buf,
    const __nv_bfloat16* AH, const __nv_bfloat16* AL,
    const __nv_bfloat16* BH, const __nv_bfloat16* BL,
    int aT, int bT)
{
    if (threadIdx.x == 0) {
        unsigned mbar = buf ? pp.mb1 : pp.mb0;
        mbar_expect(mbar, (unsigned)BUFSZ);
        unsigned d = sm32(pp.sm + buf * BUFSZ);
        bulk8k(d,             (const char*)AH + (size_t)aT * TILEB, mbar);
        bulk8k(d + TILEB,     (const char*)AL + (size_t)aT * TILEB, mbar);
        bulk8k(d + 2 * TILEB, (const char*)BH + (size_t)bT * TILEB, mbar);
        bulk8k(d + 3 * TILEB, (const char*)BL + (size_t)bT * TILEB, mbar);
    }
}

__device__ __forceinline__ void mma_planes(float c[2][2][4], const char* sbuf,
                                           int wm, int wn, int trans) {
    int l = threadIdx.x & 31;
    #pragma unroll
    for (int kb = 0; kb < KC; kb += 16) {
        unsigned ah0[4], ah1[4], al0[4], al1[4], bh[4], bl[4];
        if (!trans) {
            int ar = (l & 7) + ((l & 8) ? 8 : 0);
            int ac = kb + ((l & 16) ? 8 : 0);
            ldsm4(ah0, swp(sbuf, 0, wm + ar, ac));
            ldsm4(ah1, swp(sbuf, 0, wm + 16 + ar, ac));
            ldsm4(al0, swp(sbuf, 1, wm + ar, ac));
            ldsm4(al1, swp(sbuf, 1, wm + 16 + ar, ac));
            int br = wn + (l & 7) + ((l & 16) ? 8 : 0);
            int bc = kb + ((l & 8) ? 8 : 0);
            ldsm4(bh, swp(sbuf, 2, br, bc));
            ldsm4(bl, swp(sbuf, 3, br, bc));
        } else {
            int tr = kb + (l & 7) + ((l & 16) ? 8 : 0);
            int ac = wm + ((l & 8) ? 8 : 0);
            ldsm4t(ah0, swp(sbuf, 0, tr, ac));
            ldsm4t(ah1, swp(sbuf, 0, tr, ac + 16));
            ldsm4t(al0, swp(sbuf, 1, tr, ac));
            ldsm4t(al1, swp(sbuf, 1, tr, ac + 16));
            int br = kb + (l & 7) + ((l & 8) ? 8 : 0);
            int bc = wn + ((l & 16) ? 8 : 0);
            ldsm4t(bh, swp(sbuf, 2, br, bc));
            ldsm4t(bl, swp(sbuf, 3, br, bc));
        }
        mma16816(c[0][0], ah0, bh[0], bh[1]);
        mma16816(c[0][1], ah0, bh[2], bh[3]);
        mma16816(c[1][0], ah1, bh[0], bh[1]);
        mma16816(c[1][1], ah1, bh[2], bh[3]);
        mma16816(c[0][0], ah0, bl[0], bl[1]);
        mma16816(c[0][1], ah0, bl[2], bl[3]);
        mma16816(c[1][0], ah1, bl[0], bl[1]);
        mma16816(c[1][1], ah1, bl[2], bl[3]);
        mma16816(c[0][0], al0, bh[0], bh[1]);
        mma16816(c[0][1], al0, bh[2], bh[3]);
        mma16816(c[1][0], al1, bh[0], bh[1]);
        mma16816(c[1][1], al1, bh[2], bh[3]);
    }
}

__device__ __forceinline__ void frags_to_Cs(float c[2][2][4], float* Cs, int wm, int wn) {
    int l = threadIdx.x & 31;
    int rr = l >> 2, cc2 = (l & 3) * 2;
    #pragma unroll
    for (int mf = 0; mf < 2; mf++)
        #pragma unroll
        for (int nf = 0; nf < 2; nf++) {
            int r = wm + mf * 16 + rr, cc = wn + nf * 8 + cc2;
            *(float2*)&Cs[r * PC + cc]       = make_float2(c[mf][nf][0], c[mf][nf][1]);
            *(float2*)&Cs[(r + 8) * PC + cc] = make_float2(c[mf][nf][2], c[mf][nf][3]);
        }
}

__device__ __forceinline__ void run_tile_acc(float c[2][2][4],
    const __nv_bfloat16* AH, const __nv_bfloat16* AL,
    const __nv_bfloat16* BH, const __nv_bfloat16* BL,
    int aBase, int aStr, int bBase, int bStr, int nch, int trans, Pipe& pp)
{
    int wid = threadIdx.x >> 5;
    int wm = (wid >> 2) * 32, wn = (wid & 3) * 16;
    stage_tiles(pp, 0, AH, AL, BH, BL, aBase, bBase);
    #pragma unroll 1
    for (int kc = 0; kc < nch; kc++) {
        int cur = kc & 1;
        if (kc < nch - 1)
            stage_tiles(pp, cur ^ 1, AH, AL, BH, BL,
                        aBase + (kc + 1) * aStr, bBase + (kc + 1) * bStr);
        unsigned mbar = cur ? pp.mb1 : pp.mb0;
        mbar_wait(mbar, (pp.par >> cur) & 1u);
        pp.par ^= 1u << cur;
        mma_planes(c, pp.sm + cur * BUFSZ, wm, wn, trans);
        __syncthreads();
    }
}

__device__ __forceinline__ void run_tile(float c[2][2][4],
    const __nv_bfloat16* AH, const __nv_bfloat16* AL,
    const __nv_bfloat16* BH, const __nv_bfloat16* BL,
    int aBase, int aStr, int bBase, int bStr, int nch, int trans, Pipe& pp)
{
    run_tile_acc(c, AH, AL, BH, BL, aBase, aStr, bBase, bStr, nch, trans, pp);
    int wid = threadIdx.x >> 5;
    frags_to_Cs(c, (float*)pp.sm, (wid >> 2) * 32, (wid & 3) * 16);
    __syncthreads();
}

// ---------------- generic tile GEMM (alpha, trace, optional fp32) -------
__device__ __noinline__ void tile_gemm(int Aid, int Bid, int Cid,
                                       int m0, int n0, float alpha,
                                       int mirror, int trSlot, int wantF32,
                                       Pipe& pp)
{
    float* Cs = (float*)pp.sm;
    int tid = threadIdx.x;
    float c[2][2][4] = {};
    run_tile(c, g_h[Aid], g_l[Aid], g_h[Bid], g_l[Bid],
             (m0 >> 6) * 8, 1, (n0 >> 6) * 8, 1, 8, 0, pp);
    float* C = g_mat[Cid];
    __nv_bfloat16* CH = g_h[Cid];
    __nv_bfloat16* CL = g_l[Cid];
    int r = tid >> 2;
    float dsum = 0.f;
    #pragma unroll
    for (int q = 0; q < 4; q++) {
        int cc = (tid & 3) * 4 + q * 16;
        float4 v = *(float4*)&Cs[r * PC + cc];
        int m = m0 + r, n = n0 + cc;
        float o[4] = {v.x * alpha, v.y * alpha, v.z * alpha, v.w * alpha};
        #pragma unroll
        for (int j = 0; j < 4; j++)
            if (m == n + j) dsum += o[j];
        if (wantF32)
            *(float4*)&C[(size_t)m * D + n] = make_float4(o[0], o[1], o[2], o[3]);
        store_hl(CH, CL, m, n, o[0], o[1], o[2], o[3]);
    }
    if (mirror) {
        #pragma unroll
        for (int q = 0; q < 4; q++) {
            int cc = (tid & 3) * 4 + q * 16;
            float o[4];
            #pragma unroll
            for (int j = 0; j < 4; j++)
                o[j] = alpha * Cs[(cc + j) * PC + r];
            int row = n0 + r, col = m0 + cc;
            if (wantF32)
                *(float4*)&C[(size_t)row * D + col] = make_float4(o[0], o[1], o[2], o[3]);
            store_hl(CH, CL, row, col, o[0], o[1], o[2], o[3]);
        }
    }
    if (trSlot >= 0) {
        __syncthreads();
        float* red = (float*)pp.sm;
        red[tid] = dsum;
        __syncthreads();
        for (int off = 128; off > 0; off >>= 1) {
            if (tid < off) red[tid] += red[tid + off];
            __syncthreads();
        }
        if (tid == 0) g_tr[trSlot][m0 >> 6] = red[0];
    }
    __syncthreads();
}

// ---------------- powA: G=S@S -> E, E2 (fp32+h/l), U tails (h/l) --------
// U = k3*E + k4*E2 (degree-4 tail multiplicand); optional second tail UZ
__device__ __noinline__ void tile_powA(int Sid, int Eid, int E2id,
                                       int UYid, float k3y, float k4y,
                                       int UZid, float k3z, float k4z,
                                       float ic, int m0, int n0, int mirror,
                                       Pipe& pp)
{
    float* Cs = (float*)pp.sm;
    int tid = threadIdx.x;
    float c[2][2][4] = {};
    run_tile(c, g_h[Sid], g_l[Sid], g_h[Sid], g_l[Sid],
             (m0 >> 6) * 8, 1, (n0 >> 6) * 8, 1, 8, 0, pp);
    const float* S = g_mat[Sid];
    float* E2f = g_mat[E2id];
    __nv_bfloat16 *Eh = g_h[Eid], *El = g_l[Eid];
    __nv_bfloat16 *E2h = g_h[E2id], *E2l = g_l[E2id];
    __nv_bfloat16 *Uyh = g_h[UYid], *Uyl = g_l[UYid];
    __nv_bfloat16 *Uzh = (UZid >= 0) ? g_h[UZid] : 0;
    __nv_bfloat16 *Uzl = (UZid >= 0) ? g_l[UZid] : 0;
    float ic2 = ic * ic;
    int r = tid >> 2;
    #pragma unroll 1
    for (int half = 0; half < (mirror ? 2 : 1); half++) {
        #pragma unroll
        for (int q = 0; q < 4; q++) {
            int cc = (tid & 3) * 4 + q * 16;
            int m, n;
            float gg[4];
            if (half == 0) {
                m = m0 + r; n = n0 + cc;
                float4 g = *(float4*)&Cs[r * PC + cc];
                gg[0] = g.x; gg[1] = g.y; gg[2] = g.z; gg[3] = g.w;
            } else {
                m = n0 + r; n = m0 + cc;
                gg[0] = Cs[(cc + 0) * PC + r]; gg[1] = Cs[(cc + 1) * PC + r];
                gg[2] = Cs[(cc + 2) * PC + r]; gg[3] = Cs[(cc + 3) * PC + r];
            }
            float4 s = __ldcg((const float4*)&S[(size_t)m * D + n]);
            float ss[4] = {s.x, s.y, s.z, s.w};
            float ev[4], e2v[4], uy[4], uz[4];
            #pragma unroll
            for (int j = 0; j < 4; j++) {
                float dia = (m == n + j) ? 1.f : 0.f;
                ev[j]  = ss[j] * ic - dia;
                e2v[j] = gg[j] * ic2 - 2.f * ss[j] * ic + dia;
                uy[j]  = k3y * ev[j] + k4y * e2v[j];
                uz[j]  = k3z * ev[j] + k4z * e2v[j];
            }
            *(float4*)&E2f[(size_t)m * D + n] = make_float4(e2v[0], e2v[1], e2v[2], e2v[3]);
            store_hl(Eh, El, m, n, ev[0], ev[1], ev[2], ev[3]);
            store_hl(E2h, E2l, m, n, e2v[0], e2v[1], e2v[2], e2v[3]);
            store_hl(Uyh, Uyl, m, n, uy[0], uy[1], uy[2], uy[3]);
            if (Uzh) store_hl(Uzh, Uzl, m, n, uz[0], uz[1], uz[2], uz[3]);
        }
    }
    __syncthreads();
}

// ---------------- polyC: C = scale*(E2@U + k0 I + k1 E + k2 E2) ---------
__device__ __noinline__ void tile_polyC(int E2id, int Uid, int Sid,
                                        float ic, float k0, float k1, float k2,
                                        float scale, int Cid,
                                        int m0, int n0, int mirror, Pipe& pp)
{
    float* Cs = (float*)pp.sm;
    int tid = threadIdx.x;
    float c[2][2][4] = {};
    run_tile(c, g_h[E2id], g_l[E2id], g_h[Uid], g_l[Uid],
             (m0 >> 6) * 8, 1, (n0 >> 6) * 8, 1, 8, 0, pp);
    const float* S = g_mat[Sid];
    const float* E2f = g_mat[E2id];
    __nv_bfloat16 *CH = g_h[Cid], *CL = g_l[Cid];
    int r = tid >> 2;
    #pragma unroll 1
    for (int half = 0; half < (mirror ? 2 : 1); half++) {
        #pragma unroll
        for (int q = 0; q < 4; q++) {
            int cc = (tid & 3) * 4 + q * 16;
            int m, n;
            float gg[4];
            if (half == 0) {
                m = m0 + r; n = n0 + cc;
                float4 g = *(float4*)&Cs[r * PC + cc];
                gg[0] = g.x; gg[1] = g.y; gg[2] = g.z; gg[3] = g.w;
            } else {
                m = n0 + r; n = m0 + cc;
                gg[0] = Cs[(cc + 0) * PC + r]; gg[1] = Cs[(cc + 1) * PC + r];
                gg[2] = Cs[(cc + 2) * PC + r]; gg[3] = Cs[(cc + 3) * PC + r];
            }
            float4 s = __ldcg((const float4*)&S[(size_t)m * D + n]);
            float4 e2 = __ldcg((const float4*)&E2f[(size_t)m * D + n]);
            float ss[4] = {s.x, s.y, s.z, s.w};
            float e2v[4] = {e2.x, e2.y, e2.z, e2.w};
            float o[4];
            #pragma unroll
            for (int j = 0; j < 4; j++) {
                float dia = (m == n + j) ? 1.f : 0.f;
                float ev = ss[j] * ic - dia;
                o[j] = scale * (gg[j] + k0 * dia + k1 * ev + k2 * e2v[j]);
            }
            store_hl(CH, CL, m, n, o[0], o[1], o[2], o[3]);
        }
    }
    __syncthreads();
}

// ---------------- polyV: V = sum_j aj*(E2j@Uj + deg<=2 base_j) ----------
__device__ __noinline__ void tile_polyV(int E20, int U0, int S0, float ic0,
                                        int E21, int U1, int S1, float ic1,
                                        float a0, float a1, int Vid,
                                        int m0, int n0, int mirror, Pipe& pp)
{
    float* Cs = (float*)pp.sm;
    int tid = threadIdx.x;
    float c[2][2][4] = {};
    run_tile_acc(c, g_h[E20], g_l[E20], g_h[U0], g_l[U0],
                 (m0 >> 6) * 8, 1, (n0 >> 6) * 8, 1, 8, 0, pp);
    float r01 = a0 / a1;
    #pragma unroll
    for (int i = 0; i < 2; i++)
        #pragma unroll
        for (int j = 0; j < 2; j++)
            #pragma unroll
            for (int k = 0; k < 4; k++)
                c[i][j][k] *= r01;
    run_tile_acc(c, g_h[E21], g_l[E21], g_h[U1], g_l[U1],
                 (m0 >> 6) * 8, 1, (n0 >> 6) * 8, 1, 8, 0, pp);
    int wid = tid >> 5;
    frags_to_Cs(c, Cs, (wid >> 2) * 32, (wid & 3) * 16);
    __syncthreads();
    const float* S0f = g_mat[S0]; const float* E20f = g_mat[E20];
    const float* S1f = g_mat[S1]; const float* E21f = g_mat[E21];
    __nv_bfloat16 *CH = g_h[Vid], *CL = g_l[Vid];
    int r = tid >> 2;
    #pragma unroll 1
    for (int half = 0; half < (mirror ? 2 : 1); half++) {
        #pragma unroll
        for (int q = 0; q < 4; q++) {
            int cc = (tid & 3) * 4 + q * 16;
            int m, n;
            float gg[4];
            if (half == 0) {
                m = m0 + r; n = n0 + cc;
                float4 g = *(float4*)&Cs[r * PC + cc];
                gg[0] = g.x; gg[1] = g.y; gg[2] = g.z; gg[3] = g.w;
            } else {
                m = n0 + r; n = m0 + cc;
                gg[0] = Cs[(cc + 0) * PC + r]; gg[1] = Cs[(cc + 1) * PC + r];
                gg[2] = Cs[(cc + 2) * PC + r]; gg[3] = Cs[(cc + 3) * PC + r];
            }
            float4 s0 = __ldcg((const float4*)&S0f[(size_t)m * D + n]);
            float4 e20 = __ldcg((const float4*)&E20f[(size_t)m * D + n]);
            float4 s1 = __ldcg((const float4*)&S1f[(size_t)m * D + n]);
            float4 e21 = __ldcg((const float4*)&E21f[(size_t)m * D + n]);
            float ss0[4] = {s0.x, s0.y, s0.z, s0.w};
            float eb0[4] = {e20.x, e20.y, e20.z, e20.w};
            float ss1[4] = {s1.x, s1.y, s1.z, s1.w};
            float eb1[4] = {e21.x, e21.y, e21.z, e21.w};
            float o[4];
            #pragma unroll
            for (int j = 0; j < 4; j++) {
                float dia = (m == n + j) ? 1.f : 0.f;
                float ev0 = ss0[j] * ic0 - dia;
                float ev1 = ss1[j] * ic1 - dia;
                float b0 = MQ0 * dia + MQ1 * ev0 + MQ2 * eb0[j];
                float b1 = MQ0 * dia + MQ1 * ev1 + MQ2 * eb1[j];
                o[j] = a1 * gg[j] + a0 * b0 + a1 * b1;
            }
            store_hl(CH, CL, m, n, o[0], o[1], o[2], o[3]);
        }
    }
    __syncthreads();
}

// ---------------- phase runners ----------------
__device__ __forceinline__ void sym_decode(int tt, int &mt, int &nt) {
    int m = 0, r = tt;
    while (r >= 8 - m) { r -= 8 - m; m++; }
    mt = m; nt = m + r;
}

__device__ __noinline__ void phase_gemm(int nj, const int* A, const int* B,
                                        const int* Cid, float alpha,
                                        int sym, int tr0, int f32, Pipe& pp) {
    int tpj = sym ? 36 : 64;
    int total = nj * tpj;
    for (int t = blockIdx.x; t < total; t += NCTA) {
        int j = t / tpj, tt = t - j * tpj;
        int mt, nt;
        if (sym) sym_decode(tt, mt, nt);
        else { mt = tt >> 3; nt = tt & 7; }
        int trSlot = (tr0 >= 0 && mt == nt) ? tr0 + j : -1;
        tile_gemm(A[j], B[j], Cid[j], mt * 64, nt * 64, alpha,
                  sym && (mt != nt), trSlot, f32, pp);
    }
}

__device__ __noinline__ void phase_powA(int nj, const int* S, const int* E,
                                        const int* E2, const int* UY,
                                        const int* UZ,
                                        float k3y, float k4y,
                                        float k3z, float k4z,
                                        const float* ic, Pipe& pp) {
    int total = nj * 36;
    for (int t = blockIdx.x; t < total; t += NCTA) {
        int j = t / 36, tt = t - j * 36;
        int mt, nt;
        sym_decode(tt, mt, nt);
        tile_powA(S[j], E[j], E2[j], UY[j], k3y, k4y, UZ[j], k3z, k4z,
                  ic[j], mt * 64, nt * 64, mt != nt, pp);
    }
}

__device__ __noinline__ void phase_polyC(int nj, const int* E2, const int* U,
                                         const int* S, const float* ic,
                                         const float* k0, const float* k1,
                                         const float* k2, const float* sc,
                                         const int* Cid, Pipe& pp) {
    int total = nj * 36;
    for (int t = blockIdx.x; t < total; t += NCTA) {
        int j = t / 36, tt = t - j * 36;
        int mt, nt;
        sym_decode(tt, mt, nt);
        tile_polyC(E2[j], U[j], S[j], ic[j], k0[j], k1[j], k2[j],
                   sc[j], Cid[j], mt * 64, nt * 64, mt != nt, pp);
    }
}

__device__ __noinline__ void phase_polyV(float ic0, float ic1, float a0, float a1,
                                         Pipe& pp) {
    for (int t = blockIdx.x; t < 36; t += NCTA) {
        int mt, nt;
        sym_decode(t, mt, nt);
        tile_polyV(ME20, MU0, BM0, ic0, ME21, MU1, BM1, ic1,
                   a0, a1, BV, mt * 64, nt * 64, mt != nt, pp);
    }
}

// ---------------- trace of COVC ----------------
__device__ __noinline__ void trace_prep_covc() {
    __shared__ float red[256];
    int t = threadIdx.x;
    red[t] = __ldcg(&g_mat[COVC][(size_t)t * (D + 1)])
           + __ldcg(&g_mat[COVC][(size_t)(t + 256) * (D + 1)]);
    __syncthreads();
    for (int off = 128; off > 0; off >>= 1) {
        if (t < off) red[t] += red[t + off];
        __syncthreads();
    }
    if (t == 0) {
        g_tr[0][0] = red[0]; g_tr[4][0] = red[0];
        for (int i = 1; i < 8; i++) { g_tr[0][i] = 0.f; g_tr[4][i] = 0.f; }
    }
}

// sqrt+invsqrt of S -> SY (sqrt), SZ (invsqrt): powA + polyC = 2 phases
__device__ void root_full(int Sid, float c, Pipe& pp) {
    float ic = 1.0f / c;
    int S1[1] = {Sid}, E1[1] = {SE}, E21[1] = {SE2};
    int UY1[1] = {SUY}, UZ1[1] = {SUZ};
    float icv[1] = {ic};
    phase_powA(1, S1, E1, E21, UY1, UZ1, SQ3, SQ4, RZ3, RZ4, icv, pp);
    gridsync();
    int E2c[2] = {SE2, SE2}, Uc[2] = {SUZ, SUY};
    int Sc[2] = {Sid, Sid}, Cc[2] = {SZ, SY};
    float icc[2] = {ic, ic};
    float k0c[2] = {RZ0, SQ0}, k1c[2] = {RZ1, SQ1}, k2c[2] = {RZ2, SQ2};
    float scc[2] = {rsqrtf(c), sqrtf(c)};
    phase_polyC(2, E2c, Uc, Sc, icc, k0c, k1c, k2c, scc, Cc, pp);
    gridsync();
}

// ---------------- persistent barycenter kernel ----------------
__global__ __launch_bounds__(256, 1) void persist_k() {
    extern __shared__ char sm_c[];
    __shared__ unsigned long long s_mbar[2];
    Pipe pp;
    pp.mb0 = sm32(&s_mbar[0]); pp.mb1 = sm32(&s_mbar[1]);
    pp.par = 0; pp.sm = sm_c;
    if (threadIdx.x == 0) { mbar_init(pp.mb0); mbar_init(pp.mb1); }
    __syncthreads();

    int A[2], B[2], C[2];

    if (blockIdx.x == 0) trace_prep_covc();
    gridsync();

    for (int it = 0; it < BARY_ITERS; it++) {
        int Sid = (it == 0) ? COVC : SIGB;
        float c = get_c(0);
        root_full(Sid, c, pp);          // SY = sqrt(S), SZ = invsqrt(S)

        // P_j = SY @ cov_j (full)
        A[0] = SY; B[0] = COVC; C[0] = BP0;
        A[1] = SY; B[1] = COVS; C[1] = BP1;
        phase_gemm(2, A, B, C, 1.f, 0, -1, 0, pp);
        gridsync();
        // M_j = P_j @ SY (sym, traces 1/2, fp32)
        A[0] = BP0; B[0] = SY; C[0] = BM0;
        A[1] = BP1; B[1] = SY; C[1] = BM1;
        phase_gemm(2, A, B, C, 1.f, 1, 1, 1, pp);
        gridsync();

        float c0 = get_c(1), c1 = get_c(2);
        float ic0 = 1.f / c0, ic1 = 1.f / c1;
        // middles: powA writes E, E2, U (sqrt tail, +-0.4 coefs)
        int Sm[2] = {BM0, BM1}, Em[2] = {ME0, ME1}, E2m[2] = {ME20, ME21};
        int UYm[2] = {MU0, MU1}, UZm[2] = {-1, -1};
        float icm[2] = {ic0, ic1};
        phase_powA(2, Sm, Em, E2m, UYm, UZm, MQ3, MQ4, 0.f, 0.f, icm, pp);
        gridsync();
        // V = 0.5*sqrt(M0) + 0.5*sqrt(M1)
        phase_polyV(ic0, ic1, 0.5f * sqrtf(c0), 0.5f * sqrtf(c1), pp);
        gridsync();

        // R = SZ @ V (full)
        A[0] = SZ; B[0] = BV; C[0] = BR0;
        phase_gemm(1, A, B, C, 1.f, 0, -1, 0, pp);
        gridsync();
        // Sigma = R @ SZ (sym, trace 0, fp32)
        A[0] = BR0; B[0] = SZ; C[0] = SIGB;
        phase_gemm(1, A, B, C, 1.f, 1, 0, 1, pp);
        gridsync();
    }

    // ---- final: M = covc^-1/2 sqrt(covc^1/2 Sigma covc^1/2) covc^-1/2 ----
    float cc = get_c(4);
    root_full(COVC, cc, pp);

    A[0] = SY; B[0] = SIGB; C[0] = BP0;
    phase_gemm(1, A, B, C, 1.f, 0, -1, 0, pp);
    gridsync();
    A[0] = BP0; B[0] = SY; C[0] = BM0;
    phase_gemm(1, A, B, C, 1.f, 1, 1, 1, pp);
    gridsync();
    float cm = get_c(1);
    float icm1 = 1.f / cm;
    {
        int S1[1] = {BM0}, E1[1] = {ME0}, E21[1] = {ME20};
        int UY1[1] = {MU0}, UZ1[1] = {-1};
        float icv[1] = {icm1};
        phase_powA(1, S1, E1, E21, UY1, UZ1, MQ3, MQ4, 0.f, 0.f, icv, pp);
        gridsync();
        int E2c[1] = {ME20}, Uc[1] = {MU0}, Sc[1] = {BM0}, Cc[1] = {ME1};
        float icc[1] = {icm1};
        float k0c[1] = {MQ0}, k1c[1] = {MQ1}, k2c[1] = {MQ2};
        float scc[1] = {sqrtf(cm)};
        phase_polyC(1, E2c, Uc, Sc, icc, k0c, k1c, k2c, scc, Cc, pp);
        gridsync();
    }

    A[0] = SZ; B[0] = ME1; C[0] = BR0;
    phase_gemm(1, A, B, C, 1.f, 0, -1, 0, pp);
    gridsync();
    A[0] = BR0; B[0] = SZ; C[0] = BT0;
    phase_gemm(1, A, B, C, 1.f, 1, -1, 0, pp);
}

// ---------------- pre-kernels ----------------
__global__ void colsum1_k(const float* __restrict__ content,
                          const float* __restrict__ style) {
    int cta = blockIdx.x, t = threadIdx.x;
    const float* x = (cta < 256) ? content : style;
    const float* base = x + (size_t)(cta & 255) * 256 * D;
    float s0 = 0.f, s1 = 0.f;
    for (int r = 0; r < 256; r++) {
        s0 += base[(size_t)r * D + t];
        s1 += base[(size_t)r * D + t + 256];
    }
    g_meanpart[cta][t] = s0;
    g_meanpart[cta][t + 256] = s1;
}

__global__ void colsum2_k() {
    int t = threadIdx.x;
    float sc = 0.f, ss = 0.f;
    for (int i = 0; i < 256; i++) {
        sc += g_meanpart[i][t];
        ss += g_meanpart[256 + i][t];
    }
    sc *= (1.0f / NROWS);
    ss *= (1.0f / NROWS);
    g_mean[0][t] = sc;
    g_mean[1][t] = ss;
    g_mean[2][t] = 0.5f * (sc + ss);
}

__global__ __launch_bounds__(256) void center_k(const float* __restrict__ content,
                                                const float* __restrict__ style) {
    int which = blockIdx.y;
    const float* x = which ? style : content;
    __nv_bfloat16* XH = which ? g_xsh : g_xch;
    __nv_bfloat16* XL = which ? g_xsl : g_xcl;
    size_t i = (size_t)blockIdx.x * 256 + threadIdx.x;
    float4 v = *((const float4*)x + i);
    int r = (int)(i >> 7);
    int col = (int)((i << 2) & 511);
    float4 mu = *(const float4*)&g_mean[which][col];
    store_hl(XH, XL, r, col, v.x - mu.x, v.y - mu.y, v.z - mu.z, v.w - mu.w);
}

// ---------------- Xc^T Xc partials ----------------
__global__ __launch_bounds__(256) void xtx_k() {
    if (blockIdx.y > blockIdx.x) return;
    extern __shared__ char sm_c[];
    __shared__ unsigned long long s_mbar[2];
    Pipe pp;
    pp.mb0 = sm32(&s_mbar[0]); pp.mb1 = sm32(&s_mbar[1]);
    pp.par = 0; pp.sm = sm_c;
    if (threadIdx.x == 0) { mbar_init(pp.mb0); mbar_init(pp.mb1); }
    __syncthreads();

    float* Cs = (float*)sm_c;
    int z = blockIdx.z;
    const __nv_bfloat16* XH = (z < 32) ? g_xch : g_xsh;
    const __nv_bfloat16* XL = (z < 32) ? g_xcl : g_xsl;
    int tid = threadIdx.x;
    int m0 = blockIdx.y * 64, n0 = blockIdx.x * 64;
    int rb0 = (z & 31) * (CHUNK / 64);
    float c[2][2][4] = {};
    run_tile(c, XH, XL, XH, XL,
             rb0 * 8 + (m0 >> 6), 8, rb0 * 8 + (n0 >> 6), 8, CHUNK / 64, 1, pp);
    float* Cp = g_covpart[z];
    int r = tid >> 2;
    #pragma unroll
    for (int q = 0; q < 4; q++) {
        int cc = (tid & 3) * 4 + q * 16;
        float4 v = *(float4*)&Cs[r * PC + cc];
        *(float4*)&Cp[(m0 + r) * D + n0 + cc] = v;
    }
}

__global__ void covfin_k() {
    int gidx = blockIdx.x * 256 + threadIdx.x;
    int which = gidx >= MATN;
    int idx = gidx & (MATN - 1);
    int base = which ? 32 : 0;
    int cov = which ? COVS : COVC;
    int m = idx >> 9, n = idx & 511;
    int ms = m, ns = n;
    if ((m >> 6) > (n >> 6)) { ms = n; ns = m; }
    float s = 0.f;
    #pragma unroll 8
    for (int p = 0; p < SPLITS; p++) s += g_covpart[base + p][ms * D + ns];
    float v = s * (1.0f / (NROWS - 1));
    g_mat[cov][idx] = v;
    unsigned short h, l;
    split1(v, h, l);
    size_t t = thl_off(m, n);
    *(unsigned short*)((char*)g_h[cov] + t) = h;
    *(unsigned short*)((char*)g_l[cov] + t) = l;
}

// ---------------- output GEMM: out = Xc @ M + mu_b ----------------------
__global__ __launch_bounds__(256) void outgemm_k(float* __restrict__ out) {
    extern __shared__ char sm_c[];
    __shared__ unsigned long long s_mbar[2];
    Pipe pp;
    pp.mb0 = sm32(&s_mbar[0]); pp.mb1 = sm32(&s_mbar[1]);
    pp.par = 0; pp.sm = sm_c;
    if (threadIdx.x == 0) { mbar_init(pp.mb0); mbar_init(pp.mb1); }
    __syncthreads();

    float* Cs = (float*)sm_c;
    int tid = threadIdx.x;
    size_t m0 = (size_t)blockIdx.y * 64;
    int n0 = blockIdx.x * 64;
    float c[2][2][4] = {};
    run_tile(c, g_xch, g_xcl, g_h[BT0], g_l[BT0],
             (int)(m0 >> 6) * 8, 1, (n0 >> 6) * 8, 1, 8, 0, pp);
    int r = tid >> 2;
    #pragma unroll
    for (int q = 0; q < 4; q++) {
        int cc = (tid & 3) * 4 + q * 16;
        float4 v = *(float4*)&Cs[r * PC + cc];
        float4 mb = *(const float4*)&g_mean[2][n0 + cc];
        v.x += mb.x; v.y += mb.y; v.z += mb.z; v.w += mb.w;
        *(float4*)&out[(m0 + (size_t)r) * D + n0 + cc] = v;
    }
}

// ---------------- host orchestration ----------------
extern "C" void kernel_launch(void* const* d_in, const int* in_sizes, int n_in,
                              void* d_out, int out_size) {
    const float* content = (const float*)d_in[0];
    const float* style   = (const float*)d_in[1];
    float* out = (float*)d_out;

    cudaFuncSetAttribute(persist_k, cudaFuncAttributeMaxDynamicSharedMemorySize, SMEM_DYN);
    cudaFuncSetAttribute(xtx_k, cudaFuncAttributeMaxDynamicSharedMemorySize, SMEM_DYN);
    cudaFuncSetAttribute(outgemm_k, cudaFuncAttributeMaxDynamicSharedMemorySize, SMEM_DYN);

    colsum1_k<<<512, 256>>>(content, style);                         // 0
    colsum2_k<<<1, D>>>();                                           // 1
    center_k<<<dim3(NROWS * D / 4 / 256, 2), 256>>>(content, style); // 2
    xtx_k<<<dim3(8, 8, 64), 256, SMEM_DYN>>>();                      // 3
    covfin_k<<<2 * MATN / 256, 256>>>();                             // 4
    persist_k<<<NCTA, 256, SMEM_DYN>>>();                            // 5
    outgemm_k<<<dim3(8, 1024), 256, SMEM_DYN>>>(out);                // 6

    (void)in_sizes; (void)n_in; (void)out_size;
}

// round 17
// speedup vs baseline: 1.1647x; 1.0435x over previous
#include <cuda_runtime.h>
#include <cuda_bf16.h>
#include <math.h>

#define D 512
#define NROWS 65536
#define MATN (D*D)
#define BARY_ITERS 5
#define SPLITS 32
#define CHUNK (NROWS/SPLITS)
#define NCTA 148
#define KC 64
#define PC 68
#define TILEB 8192
#define BUFSZ 32768
#define SMEM_DYN 65536

// deg-4 Chebyshev-economized coefficients of (1+u)^(1/2), (1+u)^(-1/2)
// Sigma-root set: economized on u in [-0.25, 0.25]
#define SQ0 0.99999984f
#define SQ1 0.499966621f
#define SQ2 (-0.124954939f)
#define SQ3 0.064636254f
#define SQ4 (-0.040985088f)
#define RZ0 1.000001721f
#define RZ1 (-0.499699593f)
#define RZ2 0.374504336f
#define RZ3 (-0.331726072f)
#define RZ4 0.294585882f
// middle-root sqrt set: economized on u in [-0.4, 0.4]
#define MQ0 0.999997375f
#define MQ1 0.49978125f
#define MQ2 (-0.124704687f)
#define MQ3 0.06796875f
#define MQ4 (-0.04398438f)

// ---------------- matrix buffer ids ----------------
enum {
  COVC=0, COVS, SIGB, SE, SE2, SUZ, SUY, SZ, SY,
  BP0, BP1, BM0, BM1,
  ME0, ME20, MU0, ME1, ME21, MU1,
  BV, BR0, BT0, NBUF
};

__device__ float g_mat[NBUF][MATN];
__device__ __nv_bfloat16 g_h[NBUF][MATN];
__device__ __nv_bfloat16 g_l[NBUF][MATN];
__device__ float g_covpart[2*SPLITS][MATN];
__device__ float g_meanpart[512][D];
__device__ float g_mean[3][D];
__device__ float g_tr[5][8];
__device__ __nv_bfloat16 g_xch[(size_t)NROWS * D];
__device__ __nv_bfloat16 g_xcl[(size_t)NROWS * D];
__device__ __nv_bfloat16 g_xsh[(size_t)NROWS * D];
__device__ __nv_bfloat16 g_xsl[(size_t)NROWS * D];

// ---------------- grid-wide barrier ----------------
__device__ unsigned g_bar_cnt;
__device__ unsigned g_bar_gen;

__device__ __forceinline__ unsigned ldcg_u32(const unsigned* p) {
    unsigned v;
    asm volatile("ld.global.cg.u32 %0, [%1];" : "=r"(v) : "l"(p) : "memory");
    return v;
}

__device__ __forceinline__ void gridsync() {
    __syncthreads();
    if (threadIdx.x == 0) {
        __threadfence();
        unsigned gen = ldcg_u32(&g_bar_gen);
        if (atomicAdd(&g_bar_cnt, 1u) == NCTA - 1u) {
            g_bar_cnt = 0u;
            __threadfence();
            atomicExch(&g_bar_gen, gen + 1u);
        } else {
            unsigned ns = 32;
            while (ldcg_u32(&g_bar_gen) == gen) {
                __nanosleep(ns);
                if (ns < 256) ns <<= 1;
            }
        }
        __threadfence();
    }
    __syncthreads();
}

// ---------------- low-level helpers ----------------
__device__ __forceinline__ unsigned sm32(const void* p) {
    return (unsigned)__cvta_generic_to_shared(p);
}
__device__ __forceinline__ void mbar_init(unsigned a) {
    asm volatile("mbarrier.init.shared.b64 [%0], 1;" :: "r"(a) : "memory");
}
__device__ __forceinline__ void mbar_expect(unsigned a, unsigned bytes) {
    asm volatile("mbarrier.arrive.expect_tx.shared.b64 _, [%0], %1;"
                 :: "r"(a), "r"(bytes) : "memory");
}
__device__ __forceinline__ void bulk8k(unsigned sdst, const void* gsrc, unsigned mbar) {
    asm volatile("cp.async.bulk.shared::cta.global.mbarrier::complete_tx::bytes "
                 "[%0], [%1], 8192, [%2];"
                 :: "r"(sdst), "l"(gsrc), "r"(mbar) : "memory");
}
__device__ __forceinline__ void mbar_wait(unsigned mbar, unsigned parity) {
    asm volatile(
        "{\n\t.reg .pred P;\n\t"
        "MWL_%=:\n\t"
        "mbarrier.try_wait.parity.acquire.cta.shared::cta.b64 P, [%0], %1;\n\t"
        "@!P bra MWL_%=;\n\t}"
        :: "r"(mbar), "r"(parity) : "memory");
}
__device__ __forceinline__ void ldsm4(unsigned r[4], const unsigned short* p) {
    asm volatile("ldmatrix.sync.aligned.m8n8.x4.shared.b16 {%0,%1,%2,%3}, [%4];"
                 : "=r"(r[0]), "=r"(r[1]), "=r"(r[2]), "=r"(r[3]) : "r"(sm32(p)));
}
__device__ __forceinline__ void ldsm4t(unsigned r[4], const unsigned short* p) {
    asm volatile("ldmatrix.sync.aligned.m8n8.x4.trans.shared.b16 {%0,%1,%2,%3}, [%4];"
                 : "=r"(r[0]), "=r"(r[1]), "=r"(r[2]), "=r"(r[3]) : "r"(sm32(p)));
}
__device__ __forceinline__ void mma16816(float c[4], const unsigned a[4],
                                         unsigned b0, unsigned b1) {
    asm volatile(
        "mma.sync.aligned.m16n8k16.row.col.f32.bf16.bf16.f32 "
        "{%0,%1,%2,%3}, {%4,%5,%6,%7}, {%8,%9}, {%0,%1,%2,%3};\n"
        : "+f"(c[0]), "+f"(c[1]), "+f"(c[2]), "+f"(c[3])
        : "r"(a[0]), "r"(a[1]), "r"(a[2]), "r"(a[3]), "r"(b0), "r"(b1));
}
__device__ __forceinline__ void split2(float x0, float x1, unsigned &h, unsigned &l) {
    __nv_bfloat162 hh = __floats2bfloat162_rn(x0, x1);
    float r0 = x0 - __low2float(hh);
    float r1 = x1 - __high2float(hh);
    __nv_bfloat162 ll = __floats2bfloat162_rn(r0, r1);
    h = *reinterpret_cast<unsigned*>(&hh);
    l = *reinterpret_cast<unsigned*>(&ll);
}
__device__ __forceinline__ void split1(float x, unsigned short &h, unsigned short &l) {
    __nv_bfloat16 hb = __float2bfloat16_rn(x);
    float r = x - __bfloat162float(hb);
    __nv_bfloat16 lb = __float2bfloat16_rn(r);
    h = *reinterpret_cast<unsigned short*>(&hb);
    l = *reinterpret_cast<unsigned short*>(&lb);
}

__device__ __forceinline__ float get_c(int slot) {
    float s = 0.f;
    #pragma unroll
    for (int i = 0; i < 8; i++) s += __ldcg(&g_tr[slot][i]);
    return s * (1.0f / 512.0f);
}

__device__ __forceinline__ size_t thl_off(int m, int n) {
    unsigned tile = (((unsigned)m >> 6) << 3) + ((unsigned)n >> 6);
    unsigned off = (((unsigned)m & 63u) << 7) | (((unsigned)n & 63u) << 1);
    off ^= (off >> 3) & 0x70;
    return ((size_t)tile << 13) + off;
}

__device__ __forceinline__ void store_hl(__nv_bfloat16* H, __nv_bfloat16* L,
                                         int m, int n,
                                         float o0, float o1, float o2, float o3) {
    size_t t = thl_off(m, n);
    unsigned h0, l0, h1, l1;
    split2(o0, o1, h0, l0);
    split2(o2, o3, h1, l1);
    *(unsigned*)((char*)H + t)     = h0;
    *(unsigned*)((char*)H + t + 4) = h1;
    *(unsigned*)((char*)L + t)     = l0;
    *(unsigned*)((char*)L + t + 4) = l1;
}

__device__ __forceinline__ const unsigned short* swp(const char* sbuf, int plane,
                                                     int r, int c) {
    unsigned off = (((unsigned)r) << 7) + (((unsigned)c) << 1);
    off ^= (off >> 3) & 0x70;
    return (const unsigned short*)(sbuf + plane * TILEB + off);
}

// ---------------- pipeline ----------------
struct Pipe {
    unsigned mb0, mb1;
    unsigned par;
    char* sm;
};

__device__ __forceinline__ void stage_tiles(Pipe& pp, int buf,
    const __nv_bfloat16* AH, const __nv_bfloat16* AL,
    const __nv_bfloat16* BH, const __nv_bfloat16* BL,
    int aT, int bT)
{
    if (threadIdx.x == 0) {
        unsigned mbar = buf ? pp.mb1 : pp.mb0;
        mbar_expect(mbar, (unsigned)BUFSZ);
        unsigned d = sm32(pp.sm + buf * BUFSZ);
        bulk8k(d,             (const char*)AH + (size_t)aT * TILEB, mbar);
        bulk8k(d + TILEB,     (const char*)AL + (size_t)aT * TILEB, mbar);
        bulk8k(d + 2 * TILEB, (const char*)BH + (size_t)bT * TILEB, mbar);
        bulk8k(d + 3 * TILEB, (const char*)BL + (size_t)bT * TILEB, mbar);
    }
}

__device__ __forceinline__ void mma_planes(float c[2][2][4], const char* sbuf,
                                           int wm, int wn, int trans) {
    int l = threadIdx.x & 31;
    #pragma unroll
    for (int kb = 0; kb < KC; kb += 16) {
        unsigned ah0[4], ah1[4], al0[4], al1[4], bh[4], bl[4];
        if (!trans) {
            int ar = (l & 7) + ((l & 8) ? 8 : 0);
            int ac = kb + ((l & 16) ? 8 : 0);
            ldsm4(ah0, swp(sbuf, 0, wm + ar, ac));
            ldsm4(ah1, swp(sbuf, 0, wm + 16 + ar, ac));
            ldsm4(al0, swp(sbuf, 1, wm + ar, ac));
            ldsm4(al1, swp(sbuf, 1, wm + 16 + ar, ac));
            int br = wn + (l & 7) + ((l & 16) ? 8 : 0);
            int bc = kb + ((l & 8) ? 8 : 0);
            ldsm4(bh, swp(sbuf, 2, br, bc));
            ldsm4(bl, swp(sbuf, 3, br, bc));
        } else {
            int tr = kb + (l & 7) + ((l & 16) ? 8 : 0);
            int ac = wm + ((l & 8) ? 8 : 0);
            ldsm4t(ah0, swp(sbuf, 0, tr, ac));
            ldsm4t(ah1, swp(sbuf, 0, tr, ac + 16));
            ldsm4t(al0, swp(sbuf, 1, tr, ac));
            ldsm4t(al1, swp(sbuf, 1, tr, ac + 16));
            int br = kb + (l & 7) + ((l & 8) ? 8 : 0);
            int bc = wn + ((l & 16) ? 8 : 0);
            ldsm4t(bh, swp(sbuf, 2, br, bc));
            ldsm4t(bl, swp(sbuf, 3, br, bc));
        }
        mma16816(c[0][0], ah0, bh[0], bh[1]);
        mma16816(c[0][1], ah0, bh[2], bh[3]);
        mma16816(c[1][0], ah1, bh[0], bh[1]);
        mma16816(c[1][1], ah1, bh[2], bh[3]);
        mma16816(c[0][0], ah0, bl[0], bl[1]);
        mma16816(c[0][1], ah0, bl[2], bl[3]);
        mma16816(c[1][0], ah1, bl[0], bl[1]);
        mma16816(c[1][1], ah1, bl[2], bl[3]);
        mma16816(c[0][0], al0, bh[0], bh[1]);
        mma16816(c[0][1], al0, bh[2], bh[3]);
        mma16816(c[1][0], al1, bh[0], bh[1]);
        mma16816(c[1][1], al1, bh[2], bh[3]);
    }
}

__device__ __forceinline__ void frags_to_Cs(float c[2][2][4], float* Cs, int wm, int wn) {
    int l = threadIdx.x & 31;
    int rr = l >> 2, cc2 = (l & 3) * 2;
    #pragma unroll
    for (int mf = 0; mf < 2; mf++)
        #pragma unroll
        for (int nf = 0; nf < 2; nf++) {
            int r = wm + mf * 16 + rr, cc = wn + nf * 8 + cc2;
            *(float2*)&Cs[r * PC + cc]       = make_float2(c[mf][nf][0], c[mf][nf][1]);
            *(float2*)&Cs[(r + 8) * PC + cc] = make_float2(c[mf][nf][2], c[mf][nf][3]);
        }
}

__device__ __forceinline__ void run_tile_acc(float c[2][2][4],
    const __nv_bfloat16* AH, const __nv_bfloat16* AL,
    const __nv_bfloat16* BH, const __nv_bfloat16* BL,
    int aBase, int aStr, int bBase, int bStr, int nch, int trans, Pipe& pp)
{
    int wid = threadIdx.x >> 5;
    int wm = (wid >> 2) * 32, wn = (wid & 3) * 16;
    stage_tiles(pp, 0, AH, AL, BH, BL, aBase, bBase);
    #pragma unroll 1
    for (int kc = 0; kc < nch; kc++) {
        int cur = kc & 1;
        if (kc < nch - 1)
            stage_tiles(pp, cur ^ 1, AH, AL, BH, BL,
                        aBase + (kc + 1) * aStr, bBase + (kc + 1) * bStr);
        unsigned mbar = cur ? pp.mb1 : pp.mb0;
        mbar_wait(mbar, (pp.par >> cur) & 1u);
        pp.par ^= 1u << cur;
        mma_planes(c, pp.sm + cur * BUFSZ, wm, wn, trans);
        __syncthreads();
    }
}

__device__ __forceinline__ void run_tile(float c[2][2][4],
    const __nv_bfloat16* AH, const __nv_bfloat16* AL,
    const __nv_bfloat16* BH, const __nv_bfloat16* BL,
    int aBase, int aStr, int bBase, int bStr, int nch, int trans, Pipe& pp)
{
    run_tile_acc(c, AH, AL, BH, BL, aBase, aStr, bBase, bStr, nch, trans, pp);
    int wid = threadIdx.x >> 5;
    frags_to_Cs(c, (float*)pp.sm, (wid >> 2) * 32, (wid & 3) * 16);
    __syncthreads();
}

// ---------------- generic tile GEMM (alpha, trace, optional fp32) -------
__device__ __noinline__ void tile_gemm(int Aid, int Bid, int Cid,
                                       int m0, int n0, float alpha,
                                       int mirror, int trSlot, int wantF32,
                                       Pipe& pp)
{
    float* Cs = (float*)pp.sm;
    int tid = threadIdx.x;
    float c[2][2][4] = {};
    run_tile(c, g_h[Aid], g_l[Aid], g_h[Bid], g_l[Bid],
             (m0 >> 6) * 8, 1, (n0 >> 6) * 8, 1, 8, 0, pp);
    float* C = g_mat[Cid];
    __nv_bfloat16* CH = g_h[Cid];
    __nv_bfloat16* CL = g_l[Cid];
    int r = tid >> 2;
    float dsum = 0.f;
    #pragma unroll
    for (int q = 0; q < 4; q++) {
        int cc = (tid & 3) * 4 + q * 16;
        float4 v = *(float4*)&Cs[r * PC + cc];
        int m = m0 + r, n = n0 + cc;
        float o[4] = {v.x * alpha, v.y * alpha, v.z * alpha, v.w * alpha};
        #pragma unroll
        for (int j = 0; j < 4; j++)
            if (m == n + j) dsum += o[j];
        if (wantF32)
            *(float4*)&C[(size_t)m * D + n] = make_float4(o[0], o[1], o[2], o[3]);
        store_hl(CH, CL, m, n, o[0], o[1], o[2], o[3]);
    }
    if (mirror) {
        #pragma unroll
        for (int q = 0; q < 4; q++) {
            int cc = (tid & 3) * 4 + q * 16;
            float o[4];
            #pragma unroll
            for (int j = 0; j < 4; j++)
                o[j] = alpha * Cs[(cc + j) * PC + r];
            int row = n0 + r, col = m0 + cc;
            if (wantF32)
                *(float4*)&C[(size_t)row * D + col] = make_float4(o[0], o[1], o[2], o[3]);
            store_hl(CH, CL, row, col, o[0], o[1], o[2], o[3]);
        }
    }
    if (trSlot >= 0) {
        __syncthreads();
        float* red = (float*)pp.sm;
        red[tid] = dsum;
        __syncthreads();
        for (int off = 128; off > 0; off >>= 1) {
            if (tid < off) red[tid] += red[tid + off];
            __syncthreads();
        }
        if (tid == 0) g_tr[trSlot][m0 >> 6] = red[0];
    }
    __syncthreads();
}

// ---------------- powA: G=S@S -> E, E2 (fp32+h/l), U tails (h/l) --------
__device__ __noinline__ void tile_powA(int Sid, int Eid, int E2id,
                                       int UYid, float k3y, float k4y,
                                       int UZid, float k3z, float k4z,
                                       float ic, int m0, int n0, int mirror,
                                       Pipe& pp)
{
    float* Cs = (float*)pp.sm;
    int tid = threadIdx.x;
    float c[2][2][4] = {};
    run_tile(c, g_h[Sid], g_l[Sid], g_h[Sid], g_l[Sid],
             (m0 >> 6) * 8, 1, (n0 >> 6) * 8, 1, 8, 0, pp);
    const float* S = g_mat[Sid];
    float* E2f = g_mat[E2id];
    __nv_bfloat16 *Eh = g_h[Eid], *El = g_l[Eid];
    __nv_bfloat16 *E2h = g_h[E2id], *E2l = g_l[E2id];
    __nv_bfloat16 *Uyh = g_h[UYid], *Uyl = g_l[UYid];
    __nv_bfloat16 *Uzh = (UZid >= 0) ? g_h[UZid] : 0;
    __nv_bfloat16 *Uzl = (UZid >= 0) ? g_l[UZid] : 0;
    float ic2 = ic * ic;
    int r = tid >> 2;
    #pragma unroll 1
    for (int half = 0; half < (mirror ? 2 : 1); half++) {
        #pragma unroll
        for (int q = 0; q < 4; q++) {
            int cc = (tid & 3) * 4 + q * 16;
            int m, n;
            float gg[4];
            if (half == 0) {
                m = m0 + r; n = n0 + cc;
                float4 g = *(float4*)&Cs[r * PC + cc];
                gg[0] = g.x; gg[1] = g.y; gg[2] = g.z; gg[3] = g.w;
            } else {
                m = n0 + r; n = m0 + cc;
                gg[0] = Cs[(cc + 0) * PC + r]; gg[1] = Cs[(cc + 1) * PC + r];
                gg[2] = Cs[(cc + 2) * PC + r]; gg[3] = Cs[(cc + 3) * PC + r];
            }
            float4 s = __ldcg((const float4*)&S[(size_t)m * D + n]);
            float ss[4] = {s.x, s.y, s.z, s.w};
            float ev[4], e2v[4], uy[4], uz[4];
            #pragma unroll
            for (int j = 0; j < 4; j++) {
                float dia = (m == n + j) ? 1.f : 0.f;
                ev[j]  = ss[j] * ic - dia;
                e2v[j] = gg[j] * ic2 - 2.f * ss[j] * ic + dia;
                uy[j]  = k3y * ev[j] + k4y * e2v[j];
                uz[j]  = k3z * ev[j] + k4z * e2v[j];
            }
            *(float4*)&E2f[(size_t)m * D + n] = make_float4(e2v[0], e2v[1], e2v[2], e2v[3]);
            store_hl(Eh, El, m, n, ev[0], ev[1], ev[2], ev[3]);
            store_hl(E2h, E2l, m, n, e2v[0], e2v[1], e2v[2], e2v[3]);
            store_hl(Uyh, Uyl, m, n, uy[0], uy[1], uy[2], uy[3]);
            if (Uzh) store_hl(Uzh, Uzl, m, n, uz[0], uz[1], uz[2], uz[3]);
        }
    }
    __syncthreads();
}

// ---------------- polyC: C = scale*(E2@U + k0 I + k1 E + k2 E2) ---------
__device__ __noinline__ void tile_polyC(int E2id, int Uid, int Sid,
                                        float ic, float k0, float k1, float k2,
                                        float scale, int Cid,
                                        int m0, int n0, int mirror, Pipe& pp)
{
    float* Cs = (float*)pp.sm;
    int tid = threadIdx.x;
    float c[2][2][4] = {};
    run_tile(c, g_h[E2id], g_l[E2id], g_h[Uid], g_l[Uid],
             (m0 >> 6) * 8, 1, (n0 >> 6) * 8, 1, 8, 0, pp);
    const float* S = g_mat[Sid];
    const float* E2f = g_mat[E2id];
    __nv_bfloat16 *CH = g_h[Cid], *CL = g_l[Cid];
    int r = tid >> 2;
    #pragma unroll 1
    for (int half = 0; half < (mirror ? 2 : 1); half++) {
        #pragma unroll
        for (int q = 0; q < 4; q++) {
            int cc = (tid & 3) * 4 + q * 16;
            int m, n;
            float gg[4];
            if (half == 0) {
                m = m0 + r; n = n0 + cc;
                float4 g = *(float4*)&Cs[r * PC + cc];
                gg[0] = g.x; gg[1] = g.y; gg[2] = g.z; gg[3] = g.w;
            } else {
                m = n0 + r; n = m0 + cc;
                gg[0] = Cs[(cc + 0) * PC + r]; gg[1] = Cs[(cc + 1) * PC + r];
                gg[2] = Cs[(cc + 2) * PC + r]; gg[3] = Cs[(cc + 3) * PC + r];
            }
            float4 s = __ldcg((const float4*)&S[(size_t)m * D + n]);
            float4 e2 = __ldcg((const float4*)&E2f[(size_t)m * D + n]);
            float ss[4] = {s.x, s.y, s.z, s.w};
            float e2v[4] = {e2.x, e2.y, e2.z, e2.w};
            float o[4];
            #pragma unroll
            for (int j = 0; j < 4; j++) {
                float dia = (m == n + j) ? 1.f : 0.f;
                float ev = ss[j] * ic - dia;
                o[j] = scale * (gg[j] + k0 * dia + k1 * ev + k2 * e2v[j]);
            }
            store_hl(CH, CL, m, n, o[0], o[1], o[2], o[3]);
        }
    }
    __syncthreads();
}

// ---------------- polyV: V = sum_j aj*(E2j@Uj + deg<=2 base_j) ----------
__device__ __noinline__ void tile_polyV(int E20, int U0, int S0, float ic0,
                                        int E21, int U1, int S1, float ic1,
                                        float a0, float a1, int Vid,
                                        int m0, int n0, int mirror, Pipe& pp)
{
    float* Cs = (float*)pp.sm;
    int tid = threadIdx.x;
    float c[2][2][4] = {};
    run_tile_acc(c, g_h[E20], g_l[E20], g_h[U0], g_l[U0],
                 (m0 >> 6) * 8, 1, (n0 >> 6) * 8, 1, 8, 0, pp);
    float r01 = a0 / a1;
    #pragma unroll
    for (int i = 0; i < 2; i++)
        #pragma unroll
        for (int j = 0; j < 2; j++)
            #pragma unroll
            for (int k = 0; k < 4; k++)
                c[i][j][k] *= r01;
    run_tile_acc(c, g_h[E21], g_l[E21], g_h[U1], g_l[U1],
                 (m0 >> 6) * 8, 1, (n0 >> 6) * 8, 1, 8, 0, pp);
    int wid = tid >> 5;
    frags_to_Cs(c, Cs, (wid >> 2) * 32, (wid & 3) * 16);
    __syncthreads();
    const float* S0f = g_mat[S0]; const float* E20f = g_mat[E20];
    const float* S1f = g_mat[S1]; const float* E21f = g_mat[E21];
    __nv_bfloat16 *CH = g_h[Vid], *CL = g_l[Vid];
    int r = tid >> 2;
    #pragma unroll 1
    for (int half = 0; half < (mirror ? 2 : 1); half++) {
        #pragma unroll
        for (int q = 0; q < 4; q++) {
            int cc = (tid & 3) * 4 + q * 16;
            int m, n;
            float gg[4];
            if (half == 0) {
                m = m0 + r; n = n0 + cc;
                float4 g = *(float4*)&Cs[r * PC + cc];
                gg[0] = g.x; gg[1] = g.y; gg[2] = g.z; gg[3] = g.w;
            } else {
                m = n0 + r; n = m0 + cc;
                gg[0] = Cs[(cc + 0) * PC + r]; gg[1] = Cs[(cc + 1) * PC + r];
                gg[2] = Cs[(cc + 2) * PC + r]; gg[3] = Cs[(cc + 3) * PC + r];
            }
            float4 s0 = __ldcg((const float4*)&S0f[(size_t)m * D + n]);
            float4 e20 = __ldcg((const float4*)&E20f[(size_t)m * D + n]);
            float4 s1 = __ldcg((const float4*)&S1f[(size_t)m * D + n]);
            float4 e21 = __ldcg((const float4*)&E21f[(size_t)m * D + n]);
            float ss0[4] = {s0.x, s0.y, s0.z, s0.w};
            float eb0[4] = {e20.x, e20.y, e20.z, e20.w};
            float ss1[4] = {s1.x, s1.y, s1.z, s1.w};
            float eb1[4] = {e21.x, e21.y, e21.z, e21.w};
            float o[4];
            #pragma unroll
            for (int j = 0; j < 4; j++) {
                float dia = (m == n + j) ? 1.f : 0.f;
                float ev0 = ss0[j] * ic0 - dia;
                float ev1 = ss1[j] * ic1 - dia;
                float b0 = MQ0 * dia + MQ1 * ev0 + MQ2 * eb0[j];
                float b1 = MQ0 * dia + MQ1 * ev1 + MQ2 * eb1[j];
                o[j] = a1 * gg[j] + a0 * b0 + a1 * b1;
            }
            store_hl(CH, CL, m, n, o[0], o[1], o[2], o[3]);
        }
    }
    __syncthreads();
}

// ---------------- phase runners ----------------
__device__ __forceinline__ void sym_decode(int tt, int &mt, int &nt) {
    int m = 0, r = tt;
    while (r >= 8 - m) { r -= 8 - m; m++; }
    mt = m; nt = m + r;
}

__device__ __noinline__ void phase_gemm(int nj, const int* A, const int* B,
                                        const int* Cid, float alpha,
                                        int sym, int tr0, int f32, Pipe& pp) {
    int tpj = sym ? 36 : 64;
    int total = nj * tpj;
    for (int t = blockIdx.x; t < total; t += NCTA) {
        int j = t / tpj, tt = t - j * tpj;
        int mt, nt;
        if (sym) sym_decode(tt, mt, nt);
        else { mt = tt >> 3; nt = tt & 7; }
        int trSlot = (tr0 >= 0 && mt == nt) ? tr0 + j : -1;
        tile_gemm(A[j], B[j], Cid[j], mt * 64, nt * 64, alpha,
                  sym && (mt != nt), trSlot, f32, pp);
    }
}

__device__ __noinline__ void phase_powA(int nj, const int* S, const int* E,
                                        const int* E2, const int* UY,
                                        const int* UZ,
                                        float k3y, float k4y,
                                        float k3z, float k4z,
                                        const float* ic, Pipe& pp) {
    int total = nj * 36;
    for (int t = blockIdx.x; t < total; t += NCTA) {
        int j = t / 36, tt = t - j * 36;
        int mt, nt;
        sym_decode(tt, mt, nt);
        tile_powA(S[j], E[j], E2[j], UY[j], k3y, k4y, UZ[j], k3z, k4z,
                  ic[j], mt * 64, nt * 64, mt != nt, pp);
    }
}

__device__ __noinline__ void phase_polyC(int nj, const int* E2, const int* U,
                                         const int* S, const float* ic,
                                         const float* k0, const float* k1,
                                         const float* k2, const float* sc,
                                         const int* Cid, Pipe& pp) {
    int total = nj * 36;
    for (int t = blockIdx.x; t < total; t += NCTA) {
        int j = t / 36, tt = t - j * 36;
        int mt, nt;
        sym_decode(tt, mt, nt);
        tile_polyC(E2[j], U[j], S[j], ic[j], k0[j], k1[j], k2[j],
                   sc[j], Cid[j], mt * 64, nt * 64, mt != nt, pp);
    }
}

__device__ __noinline__ void phase_polyV(int E20, int U0, int S0, float ic0,
                                         int E21, int U1, int S1, float ic1,
                                         float a0, float a1, int Vid, Pipe& pp) {
    for (int t = blockIdx.x; t < 36; t += NCTA) {
        int mt, nt;
        sym_decode(t, mt, nt);
        tile_polyV(E20, U0, S0, ic0, E21, U1, S1, ic1,
                   a0, a1, Vid, mt * 64, nt * 64, mt != nt, pp);
    }
}

// ---------------- traces of COVC and COVS ----------------
__device__ __noinline__ void trace_prep_covs() {
    __shared__ float red[256];
    int t = threadIdx.x;
    red[t] = __ldcg(&g_mat[COVC][(size_t)t * (D + 1)])
           + __ldcg(&g_mat[COVC][(size_t)(t + 256) * (D + 1)]);
    __syncthreads();
    for (int off = 128; off > 0; off >>= 1) {
        if (t < off) red[t] += red[t + off];
        __syncthreads();
    }
    if (t == 0) {
        g_tr[4][0] = red[0];
        for (int i = 1; i < 8; i++) g_tr[4][i] = 0.f;
    }
    __syncthreads();
    red[t] = __ldcg(&g_mat[COVS][(size_t)t * (D + 1)])
           + __ldcg(&g_mat[COVS][(size_t)(t + 256) * (D + 1)]);
    __syncthreads();
    for (int off = 128; off > 0; off >>= 1) {
        if (t < off) red[t] += red[t + off];
        __syncthreads();
    }
    if (t == 0) {
        g_tr[3][0] = red[0];
        for (int i = 1; i < 8; i++) g_tr[3][i] = 0.f;
    }
}

// sqrt+invsqrt of S -> SY (sqrt), SZ (invsqrt): powA + polyC = 2 phases
__device__ void root_full(int Sid, float c, Pipe& pp) {
    float ic = 1.0f / c;
    int S1[1] = {Sid}, E1[1] = {SE}, E21[1] = {SE2};
    int UY1[1] = {SUY}, UZ1[1] = {SUZ};
    float icv[1] = {ic};
    phase_powA(1, S1, E1, E21, UY1, UZ1, SQ3, SQ4, RZ3, RZ4, icv, pp);
    gridsync();
    int E2c[2] = {SE2, SE2}, Uc[2] = {SUZ, SUY};
    int Sc[2] = {Sid, Sid}, Cc[2] = {SZ, SY};
    float icc[2] = {ic, ic};
    float k0c[2] = {RZ0, SQ0}, k1c[2] = {RZ1, SQ1}, k2c[2] = {RZ2, SQ2};
    float scc[2] = {rsqrtf(c), sqrtf(c)};
    phase_polyC(2, E2c, Uc, Sc, icc, k0c, k1c, k2c, scc, Cc, pp);
    gridsync();
}

// ---------------- persistent barycenter kernel ----------------
__global__ __launch_bounds__(256, 1) void persist_k() {
    extern __shared__ char sm_c[];
    __shared__ unsigned long long s_mbar[2];
    Pipe pp;
    pp.mb0 = sm32(&s_mbar[0]); pp.mb1 = sm32(&s_mbar[1]);
    pp.par = 0; pp.sm = sm_c;
    if (threadIdx.x == 0) { mbar_init(pp.mb0); mbar_init(pp.mb1); }
    __syncthreads();

    int A[2], B[2], C[2];

    if (blockIdx.x == 0) trace_prep_covs();
    gridsync();

    // ---- init: Sigma0 = A^2, A = 0.5*sqrt(covc) + 0.5*sqrt(covs) ----
    float ccv = get_c(4), csv = get_c(3);
    {
        float icc0 = 1.f / ccv, ics0 = 1.f / csv;
        int Si[2] = {COVC, COVS}, Ei[2] = {ME0, ME1}, E2i[2] = {ME20, ME21};
        int UYi[2] = {MU0, MU1}, UZi[2] = {-1, -1};
        float ici[2] = {icc0, ics0};
        phase_powA(2, Si, Ei, E2i, UYi, UZi, MQ3, MQ4, 0.f, 0.f, ici, pp);
        gridsync();
        phase_polyV(ME20, MU0, COVC, icc0, ME21, MU1, COVS, ics0,
                    0.5f * sqrtf(ccv), 0.5f * sqrtf(csv), BV, pp);
        gridsync();
        A[0] = BV; B[0] = BV; C[0] = SIGB;
        phase_gemm(1, A, B, C, 1.f, 1, 0, 1, pp);   // Sigma0 + trace slot 0
        gridsync();
    }

    for (int it = 0; it < BARY_ITERS; it++) {
        float c = get_c(0);
        root_full(SIGB, c, pp);         // SY = sqrt(Sigma), SZ = invsqrt(Sigma)

        // P_j = SY @ cov_j (full)
        A[0] = SY; B[0] = COVC; C[0] = BP0;
        A[1] = SY; B[1] = COVS; C[1] = BP1;
        phase_gemm(2, A, B, C, 1.f, 0, -1, 0, pp);
        gridsync();
        // M_j = P_j @ SY (sym, traces 1/2, fp32)
        A[0] = BP0; B[0] = SY; C[0] = BM0;
        A[1] = BP1; B[1] = SY; C[1] = BM1;
        phase_gemm(2, A, B, C, 1.f, 1, 1, 1, pp);
        gridsync();

        float c0 = get_c(1), c1 = get_c(2);
        float ic0 = 1.f / c0, ic1 = 1.f / c1;
        int Sm[2] = {BM0, BM1}, Em[2] = {ME0, ME1}, E2m[2] = {ME20, ME21};
        int UYm[2] = {MU0, MU1}, UZm[2] = {-1, -1};
        float icm[2] = {ic0, ic1};
        phase_powA(2, Sm, Em, E2m, UYm, UZm, MQ3, MQ4, 0.f, 0.f, icm, pp);
        gridsync();
        // V = 0.5*sqrt(M0) + 0.5*sqrt(M1)
        phase_polyV(ME20, MU0, BM0, ic0, ME21, MU1, BM1, ic1,
                    0.5f * sqrtf(c0), 0.5f * sqrtf(c1), BV, pp);
        gridsync();

        // R = SZ @ V (full)
        A[0] = SZ; B[0] = BV; C[0] = BR0;
        phase_gemm(1, A, B, C, 1.f, 0, -1, 0, pp);
        gridsync();
        // Sigma = R @ SZ (sym, trace 0, fp32)
        A[0] = BR0; B[0] = SZ; C[0] = SIGB;
        phase_gemm(1, A, B, C, 1.f, 1, 0, 1, pp);
        gridsync();
    }

    // ---- final: M = covc^-1/2 sqrt(covc^1/2 Sigma covc^1/2) covc^-1/2 ----
    root_full(COVC, ccv, pp);

    A[0] = SY; B[0] = SIGB; C[0] = BP0;
    phase_gemm(1, A, B, C, 1.f, 0, -1, 0, pp);
    gridsync();
    A[0] = BP0; B[0] = SY; C[0] = BM0;
    phase_gemm(1, A, B, C, 1.f, 1, 1, 1, pp);
    gridsync();
    float cm = get_c(1);
    float icm1 = 1.f / cm;
    {
        int S1[1] = {BM0}, E1[1] = {ME0}, E21[1] = {ME20};
        int UY1[1] = {MU0}, UZ1[1] = {-1};
        float icv[1] = {icm1};
        phase_powA(1, S1, E1, E21, UY1, UZ1, MQ3, MQ4, 0.f, 0.f, icv, pp);
        gridsync();
        int E2c[1] = {ME20}, Uc[1] = {MU0}, Sc[1] = {BM0}, Cc[1] = {ME1};
        float icc[1] = {icm1};
        float k0c[1] = {MQ0}, k1c[1] = {MQ1}, k2c[1] = {MQ2};
        float scc[1] = {sqrtf(cm)};
        phase_polyC(1, E2c, Uc, Sc, icc, k0c, k1c, k2c, scc, Cc, pp);
        gridsync();
    }

    A[0] = SZ; B[0] = ME1; C[0] = BR0;
    phase_gemm(1, A, B, C, 1.f, 0, -1, 0, pp);
    gridsync();
    A[0] = BR0; B[0] = SZ; C[0] = BT0;
    phase_gemm(1, A, B, C, 1.f, 1, -1, 0, pp);
}

// ---------------- pre-kernels ----------------
__global__ void colsum1_k(const float* __restrict__ content,
                          const float* __restrict__ style) {
    int cta = blockIdx.x, t = threadIdx.x;
    const float* x = (cta < 256) ? content : style;
    const float* base = x + (size_t)(cta & 255) * 256 * D;
    float s0 = 0.f, s1 = 0.f;
    for (int r = 0; r < 256; r++) {
        s0 += base[(size_t)r * D + t];
        s1 += base[(size_t)r * D + t + 256];
    }
    g_meanpart[cta][t] = s0;
    g_meanpart[cta][t + 256] = s1;
}

__global__ void colsum2_k() {
    int t = threadIdx.x;
    float sc = 0.f, ss = 0.f;
    for (int i = 0; i < 256; i++) {
        sc += g_meanpart[i][t];
        ss += g_meanpart[256 + i][t];
    }
    sc *= (1.0f / NROWS);
    ss *= (1.0f / NROWS);
    g_mean[0][t] = sc;
    g_mean[1][t] = ss;
    g_mean[2][t] = 0.5f * (sc + ss);
}

__global__ __launch_bounds__(256) void center_k(const float* __restrict__ content,
                                                const float* __restrict__ style) {
    int which = blockIdx.y;
    const float* x = which ? style : content;
    __nv_bfloat16* XH = which ? g_xsh : g_xch;
    __nv_bfloat16* XL = which ? g_xsl : g_xcl;
    size_t i = (size_t)blockIdx.x * 256 + threadIdx.x;
    float4 v = *((const float4*)x + i);
    int r = (int)(i >> 7);
    int col = (int)((i << 2) & 511);
    float4 mu = *(const float4*)&g_mean[which][col];
    store_hl(XH, XL, r, col, v.x - mu.x, v.y - mu.y, v.z - mu.z, v.w - mu.w);
}

// ---------------- Xc^T Xc partials ----------------
__global__ __launch_bounds__(256) void xtx_k() {
    if (blockIdx.y > blockIdx.x) return;
    extern __shared__ char sm_c[];
    __shared__ unsigned long long s_mbar[2];
    Pipe pp;
    pp.mb0 = sm32(&s_mbar[0]); pp.mb1 = sm32(&s_mbar[1]);
    pp.par = 0; pp.sm = sm_c;
    if (threadIdx.x == 0) { mbar_init(pp.mb0); mbar_init(pp.mb1); }
    __syncthreads();

    float* Cs = (float*)sm_c;
    int z = blockIdx.z;
    const __nv_bfloat16* XH = (z < 32) ? g_xch : g_xsh;
    const __nv_bfloat16* XL = (z < 32) ? g_xcl : g_xsl;
    int tid = threadIdx.x;
    int m0 = blockIdx.y * 64, n0 = blockIdx.x * 64;
    int rb0 = (z & 31) * (CHUNK / 64);
    float c[2][2][4] = {};
    run_tile(c, XH, XL, XH, XL,
             rb0 * 8 + (m0 >> 6), 8, rb0 * 8 + (n0 >> 6), 8, CHUNK / 64, 1, pp);
    float* Cp = g_covpart[z];
    int r = tid >> 2;
    #pragma unroll
    for (int q = 0; q < 4; q++) {
        int cc = (tid & 3) * 4 + q * 16;
        float4 v = *(float4*)&Cs[r * PC + cc];
        *(float4*)&Cp[(m0 + r) * D + n0 + cc] = v;
    }
}

__global__ void covfin_k() {
    int gidx = blockIdx.x * 256 + threadIdx.x;
    int which = gidx >= MATN;
    int idx = gidx & (MATN - 1);
    int base = which ? 32 : 0;
    int cov = which ? COVS : COVC;
    int m = idx >> 9, n = idx & 511;
    int ms = m, ns = n;
    if ((m >> 6) > (n >> 6)) { ms = n; ns = m; }
    float s = 0.f;
    #pragma unroll 8
    for (int p = 0; p < SPLITS; p++) s += g_covpart[base + p][ms * D + ns];
    float v = s * (1.0f / (NROWS - 1));
    g_mat[cov][idx] = v;
    unsigned short h, l;
    split1(v, h, l);
    size_t t = thl_off(m, n);
    *(unsigned short*)((char*)g_h[cov] + t) = h;
    *(unsigned short*)((char*)g_l[cov] + t) = l;
}

// ---------------- output GEMM: out = Xc @ M + mu_b ----------------------
__global__ __launch_bounds__(256) void outgemm_k(float* __restrict__ out) {
    extern __shared__ char sm_c[];
    __shared__ unsigned long long s_mbar[2];
    Pipe pp;
    pp.mb0 = sm32(&s_mbar[0]); pp.mb1 = sm32(&s_mbar[1]);
    pp.par = 0; pp.sm = sm_c;
    if (threadIdx.x == 0) { mbar_init(pp.mb0); mbar_init(pp.mb1); }
    __syncthreads();

    float* Cs = (float*)sm_c;
    int tid = threadIdx.x;
    size_t m0 = (size_t)blockIdx.y * 64;
    int n0 = blockIdx.x * 64;
    float c[2][2][4] = {};
    run_tile(c, g_xch, g_xcl, g_h[BT0], g_l[BT0],
             (int)(m0 >> 6) * 8, 1, (n0 >> 6) * 8, 1, 8, 0, pp);
    int r = tid >> 2;
    #pragma unroll
    for (int q = 0; q < 4; q++) {
        int cc = (tid & 3) * 4 + q * 16;
        float4 v = *(float4*)&Cs[r * PC + cc];
        float4 mb = *(const float4*)&g_mean[2][n0 + cc];
        v.x += mb.x; v.y += mb.y; v.z += mb.z; v.w += mb.w;
        *(float4*)&out[(m0 + (size_t)r) * D + n0 + cc] = v;
    }
}

// ---------------- host orchestration ----------------
extern "C" void kernel_launch(void* const* d_in, const int* in_sizes, int n_in,
                              void* d_out, int out_size) {
    const float* content = (const float*)d_in[0];
    const float* style   = (const float*)d_in[1];
    float* out = (float*)d_out;

    cudaFuncSetAttribute(persist_k, cudaFuncAttributeMaxDynamicSharedMemorySize, SMEM_DYN);
    cudaFuncSetAttribute(xtx_k, cudaFuncAttributeMaxDynamicSharedMemorySize, SMEM_DYN);
    cudaFuncSetAttribute(outgemm_k, cudaFuncAttributeMaxDynamicSharedMemorySize, SMEM_DYN);

    colsum1_k<<<512, 256>>>(content, style);                         // 0
    colsum2_k<<<1, D>>>();                                           // 1
    center_k<<<dim3(NROWS * D / 4 / 256, 2), 256>>>(content, style); // 2
    xtx_k<<<dim3(8, 8, 64), 256, SMEM_DYN>>>();                      // 3
    covfin_k<<<2 * MATN / 256, 256>>>();                             // 4
    persist_k<<<NCTA, 256, SMEM_DYN>>>();                            // 5
    outgemm_k<<<dim3(8, 1024), 256, SMEM_DYN>>>(out);                // 6

    (void)in_sizes; (void)n_in; (void)out_size;
}